// round 1
// baseline (speedup 1.0000x reference)
#include <cuda_runtime.h>

#define NN   100000   // nodes
#define CF   128      // feature dim (C_in == H == 128)
#define NE   1600000  // edges
#define NS   4096     // subgraphs
#define NL   64       // max subgraph size
#define NCLS 10
#define SCAN_BS 512
#define SCAN_NB ((NN + SCAN_BS - 1) / SCAN_BS)

// ---------------- scratch (no allocations allowed -> __device__ globals) ---
__device__ int   g_cnt[NN];
__device__ float g_dinv[NN];
__device__ int   g_off[NN + 1];
__device__ int   g_cur[NN];
__device__ int   g_bsum[SCAN_NB];
__device__ int   g_csr_src[NE];
__device__ float g_csr_w[NE];
__device__ float g_hw[NN * CF];   // h @ W scratch (pre-aggregation)
__device__ float g_h1[NN * CF];   // layer-1 output
__device__ float g_h2[NN * CF];   // layer-2 output
__device__ int   g_e64;           // edge_index is int64?
__device__ int   g_s64;           // subgraphs is int64?

// ---------------- dtype detection (int64 vs int32, decided on-device) ------
__global__ void k_detect(const unsigned int* __restrict__ ei,
                         const unsigned int* __restrict__ sg) {
    if (threadIdx.x == 0 && blockIdx.x == 0) {
        // int64 nonneg indices < 2^31 have zero high words; int32 data puts a
        // random index in that slot (all-zero prob ~1e-320 over 64 samples).
        int e64 = 1;
        for (int i = 0; i < 64; i++)
            if (ei[2 * i + 1] != 0u) { e64 = 0; break; }
        // subgraphs contain -1 padding: int64 high words are 0 or 0xFFFFFFFF.
        int s64 = 1;
        for (int i = 0; i < 64; i++) {
            unsigned hi = sg[2 * i + 1];
            if (hi != 0u && hi != 0xFFFFFFFFu) { s64 = 0; break; }
        }
        g_e64 = e64;
        g_s64 = s64;
    }
}

__device__ __forceinline__ int load_idx(const void* p, int i, int is64) {
    return is64 ? (int)((const long long*)p)[i] : ((const int*)p)[i];
}

// ---------------- degree / normalization -----------------------------------
__global__ void k_zero_cnt() {
    int i = blockIdx.x * blockDim.x + threadIdx.x;
    if (i < NN) g_cnt[i] = 0;
}

__global__ void k_count(const void* __restrict__ ei) {
    int e = blockIdx.x * blockDim.x + threadIdx.x;
    if (e >= NE) return;
    int d = load_idx(ei, NE + e, g_e64);   // dst = second row
    atomicAdd(&g_cnt[d], 1);
}

__global__ void k_dinv() {
    int i = blockIdx.x * blockDim.x + threadIdx.x;
    if (i < NN) g_dinv[i] = rsqrtf((float)(g_cnt[i] + 1));  // +1 self-loop
}

// ---------------- exclusive scan of counts -> CSR offsets ------------------
__global__ void k_scan1() {
    __shared__ int sm[SCAN_BS];
    int gid = blockIdx.x * SCAN_BS + threadIdx.x;
    int v = (gid < NN) ? g_cnt[gid] : 0;
    sm[threadIdx.x] = v;
    __syncthreads();
    for (int ofs = 1; ofs < SCAN_BS; ofs <<= 1) {
        int t = (threadIdx.x >= ofs) ? sm[threadIdx.x - ofs] : 0;
        __syncthreads();
        sm[threadIdx.x] += t;
        __syncthreads();
    }
    if (gid < NN) g_off[gid] = sm[threadIdx.x] - v;          // exclusive
    if (threadIdx.x == SCAN_BS - 1) g_bsum[blockIdx.x] = sm[threadIdx.x];
}

__global__ void k_scan2() {
    if (threadIdx.x == 0 && blockIdx.x == 0) {
        int run = 0;
        for (int b = 0; b < SCAN_NB; b++) {
            int t = g_bsum[b]; g_bsum[b] = run; run += t;
        }
    }
}

__global__ void k_scan3() {
    int gid = blockIdx.x * SCAN_BS + threadIdx.x;
    if (gid < NN) {
        int o = g_off[gid] + g_bsum[blockIdx.x];
        g_off[gid] = o;
        g_cur[gid] = o;
    }
    if (gid == 0) g_off[NN] = NE;
}

// ---------------- CSR fill (group edges by dst) ----------------------------
__global__ void k_fill(const void* __restrict__ ei) {
    int e = blockIdx.x * blockDim.x + threadIdx.x;
    if (e >= NE) return;
    int is64 = g_e64;
    int s = load_idx(ei, e, is64);
    int d = load_idx(ei, NE + e, is64);
    int pos = atomicAdd(&g_cur[d], 1);
    g_csr_src[pos] = s;
    g_csr_w[pos] = g_dinv[s] * g_dinv[d];
}

// ---------------- dense GEMM: O[M,128] = A[M,128] @ W[128,128] -------------
// 64x128 tile / block, 256 threads, K-chunk 16, A staged k-major in smem.
__global__ __launch_bounds__(256) void k_gemm(const float* __restrict__ Aext,
                                              const float* __restrict__ W,
                                              int src_sel /*0=Aext 1=g_h1*/) {
    __shared__ float As[16][64];
    __shared__ float Bs[16][CF];
    const float* A = (src_sel == 0) ? Aext : g_h1;
    float* O = g_hw;
    int tid = threadIdx.x;
    int row0 = blockIdx.x * 64;
    int ty = tid >> 4, tx = tid & 15;        // rows ty*4.., cols tx*8..
    int ar = tid >> 2, aq = tid & 3;         // A staging: row ar, quad aq

    float acc[4][8];
#pragma unroll
    for (int i = 0; i < 4; i++)
#pragma unroll
        for (int j = 0; j < 8; j++) acc[i][j] = 0.f;

    for (int k0 = 0; k0 < CF; k0 += 16) {
        int grow = row0 + ar;
        float4 av = make_float4(0.f, 0.f, 0.f, 0.f);
        if (grow < NN) av = *(const float4*)&A[grow * CF + k0 + aq * 4];
        As[aq * 4 + 0][ar] = av.x;
        As[aq * 4 + 1][ar] = av.y;
        As[aq * 4 + 2][ar] = av.z;
        As[aq * 4 + 3][ar] = av.w;
#pragma unroll
        for (int i = 0; i < 2; i++) {
            int t = tid + i * 256;
            int br = t >> 5, bc = t & 31;
            *(float4*)&Bs[br][bc * 4] = *(const float4*)&W[(k0 + br) * CF + bc * 4];
        }
        __syncthreads();
#pragma unroll
        for (int kk = 0; kk < 16; kk++) {
            float4 a4 = *(const float4*)&As[kk][ty * 4];
            float4 b0 = *(const float4*)&Bs[kk][tx * 8];
            float4 b1 = *(const float4*)&Bs[kk][tx * 8 + 4];
            float a[4] = {a4.x, a4.y, a4.z, a4.w};
            float b[8] = {b0.x, b0.y, b0.z, b0.w, b1.x, b1.y, b1.z, b1.w};
#pragma unroll
            for (int i = 0; i < 4; i++)
#pragma unroll
                for (int j = 0; j < 8; j++) acc[i][j] += a[i] * b[j];
        }
        __syncthreads();
    }
#pragma unroll
    for (int i = 0; i < 4; i++) {
        int r = row0 + ty * 4 + i;
        if (r < NN) {
            *(float4*)&O[r * CF + tx * 8] =
                make_float4(acc[i][0], acc[i][1], acc[i][2], acc[i][3]);
            *(float4*)&O[r * CF + tx * 8 + 4] =
                make_float4(acc[i][4], acc[i][5], acc[i][6], acc[i][7]);
        }
    }
}

// ---------------- aggregation: out[d] = sum_s hw[s]*norm + self + bias -----
// One warp per node; lane owns 4 channels (float4). Atomic-free via CSR.
__global__ __launch_bounds__(256) void k_agg(const float* __restrict__ bias,
                                             int dst_sel /*1=g_h1 2=g_h2*/,
                                             int do_relu) {
    int gw = (blockIdx.x * blockDim.x + threadIdx.x) >> 5;
    int lane = threadIdx.x & 31;
    if (gw >= NN) return;
    const float* hw = g_hw;
    float* out = (dst_sel == 1) ? g_h1 : g_h2;

    float di = g_dinv[gw];
    float ws = di * di;                       // self-loop norm
    float4 sv = *(const float4*)&hw[gw * CF + lane * 4];
    float ax = sv.x * ws, ay = sv.y * ws, az = sv.z * ws, aw = sv.w * ws;

    int e = g_off[gw], e1 = g_off[gw + 1];
    for (; e + 2 <= e1; e += 2) {
        int sA = g_csr_src[e], sB = g_csr_src[e + 1];
        float wA = g_csr_w[e], wB = g_csr_w[e + 1];
        float4 vA = *(const float4*)&hw[sA * CF + lane * 4];
        float4 vB = *(const float4*)&hw[sB * CF + lane * 4];
        ax += vA.x * wA + vB.x * wB;
        ay += vA.y * wA + vB.y * wB;
        az += vA.z * wA + vB.z * wB;
        aw += vA.w * wA + vB.w * wB;
    }
    if (e < e1) {
        int sA = g_csr_src[e];
        float wA = g_csr_w[e];
        float4 vA = *(const float4*)&hw[sA * CF + lane * 4];
        ax += vA.x * wA; ay += vA.y * wA; az += vA.z * wA; aw += vA.w * wA;
    }
    float4 b = *(const float4*)&bias[lane * 4];
    ax += b.x; ay += b.y; az += b.z; aw += b.w;
    if (do_relu) {
        ax = fmaxf(ax, 0.f); ay = fmaxf(ay, 0.f);
        az = fmaxf(az, 0.f); aw = fmaxf(aw, 0.f);
    }
    *(float4*)&out[gw * CF + lane * 4] = make_float4(ax, ay, az, aw);
}

// ---------------- subgraph mean-pool + classifier --------------------------
// One warp per subgraph; lane owns 4 channels; warp-reduce into 10 classes.
__global__ __launch_bounds__(256) void k_pool(const void* __restrict__ sg,
                                              const float* __restrict__ Wc,
                                              const float* __restrict__ bc,
                                              float* __restrict__ out) {
    int gw = (blockIdx.x * blockDim.x + threadIdx.x) >> 5;
    int lane = threadIdx.x & 31;
    if (gw >= NS) return;
    int is64 = g_s64;

    float ax = 0.f, ay = 0.f, az = 0.f, aw = 0.f;
    int cnt = 0;
    for (int l = 0; l < NL; l++) {
        int idx = load_idx(sg, gw * NL + l, is64);
        if (idx >= 0) {
            cnt++;
            float4 v = *(const float4*)&g_h2[idx * CF + lane * 4];
            ax += v.x; ay += v.y; az += v.z; aw += v.w;
        }
    }
    float inv = 1.0f / (float)(cnt > 0 ? cnt : 1);
    ax *= inv; ay *= inv; az *= inv; aw *= inv;

    float res[NCLS];
#pragma unroll
    for (int c = 0; c < NCLS; c++) {
        int k = lane * 4;
        res[c] = ax * Wc[(k + 0) * NCLS + c] + ay * Wc[(k + 1) * NCLS + c] +
                 az * Wc[(k + 2) * NCLS + c] + aw * Wc[(k + 3) * NCLS + c];
    }
#pragma unroll
    for (int c = 0; c < NCLS; c++) {
        float v = res[c];
#pragma unroll
        for (int o = 16; o > 0; o >>= 1) v += __shfl_xor_sync(0xffffffffu, v, o);
        if (lane == 0) out[gw * NCLS + c] = v + bc[c];
    }
}

// ---------------- launch ----------------------------------------------------
extern "C" void kernel_launch(void* const* d_in, const int* in_sizes, int n_in,
                              void* d_out, int out_size) {
    const float* x  = (const float*)d_in[0];   // (N,1,128) contiguous
    const void*  ei = d_in[1];                 // (2,E) int64 or int32
    const void*  sg = d_in[2];                 // (S,64) int64 or int32
    const float* W1 = (const float*)d_in[3];
    const float* b1 = (const float*)d_in[4];
    const float* W2 = (const float*)d_in[5];
    const float* b2 = (const float*)d_in[6];
    const float* Wc = (const float*)d_in[7];
    const float* bc = (const float*)d_in[8];
    float* out = (float*)d_out;

    const int TB = 256;
    const int nbN = (NN + TB - 1) / TB;
    const int nbE = (NE + TB - 1) / TB;
    const int nbG = (NN + 63) / 64;
    const int nbA = (NN * 32 + TB - 1) / TB;   // warp per node
    const int nbP = (NS * 32 + TB - 1) / TB;   // warp per subgraph

    k_detect<<<1, 32>>>((const unsigned int*)ei, (const unsigned int*)sg);
    k_zero_cnt<<<nbN, TB>>>();
    k_count<<<nbE, TB>>>(ei);
    k_dinv<<<nbN, TB>>>();
    k_scan1<<<SCAN_NB, SCAN_BS>>>();
    k_scan2<<<1, 32>>>();
    k_scan3<<<SCAN_NB, SCAN_BS>>>();
    k_fill<<<nbE, TB>>>(ei);

    // layer 1: hw = x @ W1 ; h1 = relu(agg(hw) + b1)
    k_gemm<<<nbG, TB>>>(x, W1, 0);
    k_agg<<<nbA, TB>>>(b1, 1, 1);
    // layer 2: hw = h1 @ W2 ; h2 = agg(hw) + b2
    k_gemm<<<nbG, TB>>>(x, W2, 1);
    k_agg<<<nbA, TB>>>(b2, 2, 0);
    // pool + classify
    k_pool<<<nbP, TB>>>(sg, Wc, bc, out);
}

// round 2
// speedup vs baseline: 1.2495x; 1.2495x over previous
#include <cuda_runtime.h>
#include <cstdint>

#define NN   100000   // nodes
#define CF   128      // feature dim (C_in == H == 128)
#define NE   1600000  // edges
#define NS   4096     // subgraphs
#define NL   64       // max subgraph size
#define NCLS 10
#define SCAN_BS 512
#define SCAN_NB ((NN + SCAN_BS - 1) / SCAN_BS)

// ---------------- scratch (no allocations allowed -> __device__ globals) ---
__device__ int   g_cnt[NN];        // zeroed at module load; re-zeroed per launch in k_scan3
__device__ float g_dinv[NN];
__device__ int   g_off[NN + 1];
__device__ int   g_cur[NN];
__device__ int   g_bsum[SCAN_NB];
__device__ int   g_csr_src[NE];
__device__ float g_csr_w[NE];
__device__ float g_hw[NN * CF];   // h @ W scratch (pre-aggregation)
__device__ float g_h1[NN * CF];   // layer-1 output
__device__ float g_h2[NN * CF];   // layer-2 output
__device__ int   g_e64;           // edge_index is int64?
__device__ int   g_s64;           // subgraphs is int64?

// ---------------- dtype detection (int64 vs int32, decided on-device) ------
__global__ void k_detect(const unsigned int* __restrict__ ei,
                         const unsigned int* __restrict__ sg) {
    if (threadIdx.x == 0 && blockIdx.x == 0) {
        int e64 = 1;
        for (int i = 0; i < 64; i++)
            if (ei[2 * i + 1] != 0u) { e64 = 0; break; }
        int s64 = 1;
        for (int i = 0; i < 64; i++) {
            unsigned hi = sg[2 * i + 1];
            if (hi != 0u && hi != 0xFFFFFFFFu) { s64 = 0; break; }
        }
        g_e64 = e64;
        g_s64 = s64;
    }
}

__device__ __forceinline__ int load_idx(const void* p, int i, int is64) {
    return is64 ? (int)((const long long*)p)[i] : ((const int*)p)[i];
}

// ---------------- degree count ---------------------------------------------
__global__ void k_count(const void* __restrict__ ei) {
    int e = blockIdx.x * blockDim.x + threadIdx.x;
    if (e >= NE) return;
    int d = load_idx(ei, NE + e, g_e64);   // dst = second row
    atomicAdd(&g_cnt[d], 1);
}

// ---------------- scan1: per-block exclusive scan + dinv -------------------
__global__ void k_scan1() {
    __shared__ int sm[SCAN_BS];
    int gid = blockIdx.x * SCAN_BS + threadIdx.x;
    int v = (gid < NN) ? g_cnt[gid] : 0;
    if (gid < NN) g_dinv[gid] = rsqrtf((float)(v + 1));  // +1 self-loop
    sm[threadIdx.x] = v;
    __syncthreads();
    for (int ofs = 1; ofs < SCAN_BS; ofs <<= 1) {
        int t = (threadIdx.x >= ofs) ? sm[threadIdx.x - ofs] : 0;
        __syncthreads();
        sm[threadIdx.x] += t;
        __syncthreads();
    }
    if (gid < NN) g_off[gid] = sm[threadIdx.x] - v;          // exclusive
    if (threadIdx.x == SCAN_BS - 1) g_bsum[blockIdx.x] = sm[threadIdx.x];
}

// ---------------- scan2: parallel exclusive scan of block sums -------------
__global__ void k_scan2() {
    __shared__ int sm[256];
    int tid = threadIdx.x;
    int v = (tid < SCAN_NB) ? g_bsum[tid] : 0;
    sm[tid] = v;
    __syncthreads();
    for (int ofs = 1; ofs < 256; ofs <<= 1) {
        int t = (tid >= ofs) ? sm[tid - ofs] : 0;
        __syncthreads();
        sm[tid] += t;
        __syncthreads();
    }
    if (tid < SCAN_NB) g_bsum[tid] = sm[tid] - v;            // exclusive
}

// ---------------- scan3: finalize offsets, re-zero counts ------------------
__global__ void k_scan3() {
    int gid = blockIdx.x * SCAN_BS + threadIdx.x;
    if (gid < NN) {
        int o = g_off[gid] + g_bsum[blockIdx.x];
        g_off[gid] = o;
        g_cur[gid] = o;
        g_cnt[gid] = 0;                 // ready for the next graph replay
    }
    if (gid == 0) g_off[NN] = NE;
}

// ---------------- CSR fill (group edges by dst) ----------------------------
__global__ void k_fill(const void* __restrict__ ei) {
    int e = blockIdx.x * blockDim.x + threadIdx.x;
    if (e >= NE) return;
    int is64 = g_e64;
    int s = load_idx(ei, e, is64);
    int d = load_idx(ei, NE + e, is64);
    int pos = atomicAdd(&g_cur[d], 1);
    g_csr_src[pos] = s;
    g_csr_w[pos] = g_dinv[s] * g_dinv[d];
}

// ---------------- tf32 tensor-core GEMM with hi/lo split -------------------
__device__ __forceinline__ uint32_t f2tf32(float f) {
    uint32_t u;
    asm("cvt.rna.tf32.f32 %0, %1;" : "=r"(u) : "f"(f));
    return u;
}

__device__ __forceinline__ void mma8(float& d0, float& d1, float& d2, float& d3,
                                     uint32_t a0, uint32_t a1, uint32_t a2, uint32_t a3,
                                     uint32_t b0, uint32_t b1) {
    asm volatile(
        "mma.sync.aligned.m16n8k8.row.col.f32.tf32.tf32.f32 "
        "{%0,%1,%2,%3}, {%4,%5,%6,%7}, {%8,%9}, {%0,%1,%2,%3};"
        : "+f"(d0), "+f"(d1), "+f"(d2), "+f"(d3)
        : "r"(a0), "r"(a1), "r"(a2), "r"(a3), "r"(b0), "r"(b1));
}

// O[M,128] = A[M,128] @ W[128,128], split-tf32 (3 MMAs -> ~fp32 accuracy).
// Block: 256 thr = 8 warps; tile 128 rows x 128 cols; W staged hi/lo in smem
// in 32-row K-chunks. Smem stride 136 -> bank = (8k + n) % 32, conflict-free
// for the b-fragment pattern (k = lane&3 {+4}, n = lane>>2).
__global__ __launch_bounds__(256) void k_gemm_tc(const float* __restrict__ Aext,
                                                 const float* __restrict__ W,
                                                 int src_sel /*0=Aext 1=g_h1*/) {
    __shared__ uint32_t BsHi[32][136];
    __shared__ uint32_t BsLo[32][136];
    const float* A = src_sel ? g_h1 : Aext;
    float* O = g_hw;

    int tid = threadIdx.x;
    int wid = tid >> 5, lane = tid & 31;
    int g = lane >> 2, tg = lane & 3;
    int row0 = blockIdx.x * 128 + wid * 16;
    int r0 = row0 + g, r1 = r0 + 8;
    bool v0 = r0 < NN, v1 = r1 < NN;

    float acc[16][4];
#pragma unroll
    for (int nt = 0; nt < 16; nt++)
#pragma unroll
        for (int i = 0; i < 4; i++) acc[nt][i] = 0.f;

    for (int kc = 0; kc < 4; kc++) {
        int k0c = kc * 32;
        // stage W[k0c:k0c+32, :] hi/lo into smem: 1024 float4s / 256 threads
#pragma unroll
        for (int j = 0; j < 4; j++) {
            int q = tid + j * 256;
            int br = q >> 5, bc = (q & 31) * 4;
            float4 w4 = *(const float4*)&W[(k0c + br) * CF + bc];
            uint32_t h0 = f2tf32(w4.x), h1 = f2tf32(w4.y);
            uint32_t h2 = f2tf32(w4.z), h3 = f2tf32(w4.w);
            BsHi[br][bc + 0] = h0; BsHi[br][bc + 1] = h1;
            BsHi[br][bc + 2] = h2; BsHi[br][bc + 3] = h3;
            BsLo[br][bc + 0] = f2tf32(w4.x - __uint_as_float(h0));
            BsLo[br][bc + 1] = f2tf32(w4.y - __uint_as_float(h1));
            BsLo[br][bc + 2] = f2tf32(w4.z - __uint_as_float(h2));
            BsLo[br][bc + 3] = f2tf32(w4.w - __uint_as_float(h3));
        }
        __syncthreads();
#pragma unroll
        for (int ks = 0; ks < 4; ks++) {
            int kg = k0c + ks * 8;
            float a0 = v0 ? A[r0 * CF + kg + tg] : 0.f;
            float a1 = v1 ? A[r1 * CF + kg + tg] : 0.f;
            float a2 = v0 ? A[r0 * CF + kg + tg + 4] : 0.f;
            float a3 = v1 ? A[r1 * CF + kg + tg + 4] : 0.f;
            uint32_t ah0 = f2tf32(a0), ah1 = f2tf32(a1);
            uint32_t ah2 = f2tf32(a2), ah3 = f2tf32(a3);
            uint32_t al0 = f2tf32(a0 - __uint_as_float(ah0));
            uint32_t al1 = f2tf32(a1 - __uint_as_float(ah1));
            uint32_t al2 = f2tf32(a2 - __uint_as_float(ah2));
            uint32_t al3 = f2tf32(a3 - __uint_as_float(ah3));
            int kb = ks * 8;
#pragma unroll
            for (int nt = 0; nt < 16; nt++) {
                uint32_t bh0 = BsHi[kb + tg][nt * 8 + g];
                uint32_t bh1 = BsHi[kb + tg + 4][nt * 8 + g];
                uint32_t bl0 = BsLo[kb + tg][nt * 8 + g];
                uint32_t bl1 = BsLo[kb + tg + 4][nt * 8 + g];
                mma8(acc[nt][0], acc[nt][1], acc[nt][2], acc[nt][3],
                     ah0, ah1, ah2, ah3, bh0, bh1);
                mma8(acc[nt][0], acc[nt][1], acc[nt][2], acc[nt][3],
                     al0, al1, al2, al3, bh0, bh1);
                mma8(acc[nt][0], acc[nt][1], acc[nt][2], acc[nt][3],
                     ah0, ah1, ah2, ah3, bl0, bl1);
            }
        }
        __syncthreads();
    }
#pragma unroll
    for (int nt = 0; nt < 16; nt++) {
        int c = nt * 8 + tg * 2;
        if (v0) *(float2*)&O[r0 * CF + c] = make_float2(acc[nt][0], acc[nt][1]);
        if (v1) *(float2*)&O[r1 * CF + c] = make_float2(acc[nt][2], acc[nt][3]);
    }
}

// ---------------- aggregation: out[d] = sum_s hw[s]*norm + self + bias -----
// One warp per node; lane owns 4 channels (float4). Atomic-free via CSR.
__global__ __launch_bounds__(256) void k_agg(const float* __restrict__ bias,
                                             int dst_sel /*1=g_h1 2=g_h2*/,
                                             int do_relu) {
    int gw = (blockIdx.x * blockDim.x + threadIdx.x) >> 5;
    int lane = threadIdx.x & 31;
    if (gw >= NN) return;
    const float* hw = g_hw;
    float* out = (dst_sel == 1) ? g_h1 : g_h2;

    float di = g_dinv[gw];
    float ws = di * di;                       // self-loop norm
    float4 sv = *(const float4*)&hw[gw * CF + lane * 4];
    float ax = sv.x * ws, ay = sv.y * ws, az = sv.z * ws, aw = sv.w * ws;

    int e = g_off[gw], e1 = g_off[gw + 1];
    for (; e + 4 <= e1; e += 4) {
        int sA = g_csr_src[e],     sB = g_csr_src[e + 1];
        int sC = g_csr_src[e + 2], sD = g_csr_src[e + 3];
        float wA = g_csr_w[e],     wB = g_csr_w[e + 1];
        float wC = g_csr_w[e + 2], wD = g_csr_w[e + 3];
        float4 vA = *(const float4*)&hw[sA * CF + lane * 4];
        float4 vB = *(const float4*)&hw[sB * CF + lane * 4];
        float4 vC = *(const float4*)&hw[sC * CF + lane * 4];
        float4 vD = *(const float4*)&hw[sD * CF + lane * 4];
        ax += vA.x * wA + vB.x * wB + vC.x * wC + vD.x * wD;
        ay += vA.y * wA + vB.y * wB + vC.y * wC + vD.y * wD;
        az += vA.z * wA + vB.z * wB + vC.z * wC + vD.z * wD;
        aw += vA.w * wA + vB.w * wB + vC.w * wC + vD.w * wD;
    }
    for (; e < e1; e++) {
        int sA = g_csr_src[e];
        float wA = g_csr_w[e];
        float4 vA = *(const float4*)&hw[sA * CF + lane * 4];
        ax += vA.x * wA; ay += vA.y * wA; az += vA.z * wA; aw += vA.w * wA;
    }
    float4 b = *(const float4*)&bias[lane * 4];
    ax += b.x; ay += b.y; az += b.z; aw += b.w;
    if (do_relu) {
        ax = fmaxf(ax, 0.f); ay = fmaxf(ay, 0.f);
        az = fmaxf(az, 0.f); aw = fmaxf(aw, 0.f);
    }
    *(float4*)&out[gw * CF + lane * 4] = make_float4(ax, ay, az, aw);
}

// ---------------- subgraph mean-pool + classifier --------------------------
__global__ __launch_bounds__(256) void k_pool(const void* __restrict__ sg,
                                              const float* __restrict__ Wc,
                                              const float* __restrict__ bc,
                                              float* __restrict__ out) {
    int gw = (blockIdx.x * blockDim.x + threadIdx.x) >> 5;
    int lane = threadIdx.x & 31;
    if (gw >= NS) return;
    int is64 = g_s64;

    float ax = 0.f, ay = 0.f, az = 0.f, aw = 0.f;
    int cnt = 0;
    for (int l = 0; l < NL; l++) {
        int idx = load_idx(sg, gw * NL + l, is64);
        if (idx >= 0) {
            cnt++;
            float4 v = *(const float4*)&g_h2[idx * CF + lane * 4];
            ax += v.x; ay += v.y; az += v.z; aw += v.w;
        }
    }
    float inv = 1.0f / (float)(cnt > 0 ? cnt : 1);
    ax *= inv; ay *= inv; az *= inv; aw *= inv;

    float res[NCLS];
#pragma unroll
    for (int c = 0; c < NCLS; c++) {
        int k = lane * 4;
        res[c] = ax * Wc[(k + 0) * NCLS + c] + ay * Wc[(k + 1) * NCLS + c] +
                 az * Wc[(k + 2) * NCLS + c] + aw * Wc[(k + 3) * NCLS + c];
    }
#pragma unroll
    for (int c = 0; c < NCLS; c++) {
        float v = res[c];
#pragma unroll
        for (int o = 16; o > 0; o >>= 1) v += __shfl_xor_sync(0xffffffffu, v, o);
        if (lane == 0) out[gw * NCLS + c] = v + bc[c];
    }
}

// ---------------- launch ----------------------------------------------------
extern "C" void kernel_launch(void* const* d_in, const int* in_sizes, int n_in,
                              void* d_out, int out_size) {
    const float* x  = (const float*)d_in[0];   // (N,1,128) contiguous
    const void*  ei = d_in[1];                 // (2,E) int64 or int32
    const void*  sg = d_in[2];                 // (S,64) int64 or int32
    const float* W1 = (const float*)d_in[3];
    const float* b1 = (const float*)d_in[4];
    const float* W2 = (const float*)d_in[5];
    const float* b2 = (const float*)d_in[6];
    const float* Wc = (const float*)d_in[7];
    const float* bc = (const float*)d_in[8];
    float* out = (float*)d_out;

    const int TB = 256;
    const int nbE = (NE + TB - 1) / TB;
    const int nbG = (NN + 127) / 128;
    const int nbA = (NN * 32 + TB - 1) / TB;   // warp per node
    const int nbP = (NS * 32 + TB - 1) / TB;   // warp per subgraph

    k_detect<<<1, 32>>>((const unsigned int*)ei, (const unsigned int*)sg);
    k_count<<<nbE, TB>>>(ei);                  // g_cnt pre-zeroed (init / k_scan3)
    k_scan1<<<SCAN_NB, SCAN_BS>>>();
    k_scan2<<<1, 256>>>();
    k_scan3<<<SCAN_NB, SCAN_BS>>>();
    k_fill<<<nbE, TB>>>(ei);

    // layer 1: hw = x @ W1 ; h1 = relu(agg(hw) + b1)
    k_gemm_tc<<<nbG, TB>>>(x, W1, 0);
    k_agg<<<nbA, TB>>>(b1, 1, 1);
    // layer 2: hw = h1 @ W2 ; h2 = agg(hw) + b2
    k_gemm_tc<<<nbG, TB>>>(x, W2, 1);
    k_agg<<<nbA, TB>>>(b2, 2, 0);
    // pool + classify
    k_pool<<<nbP, TB>>>(sg, Wc, bc, out);
}

// round 3
// speedup vs baseline: 1.3249x; 1.0603x over previous
#include <cuda_runtime.h>
#include <cuda_fp16.h>
#include <cstdint>

#define NN   100000   // nodes
#define CF   128      // feature dim (C_in == H == 128)
#define NE   1600000  // edges
#define NS   4096     // subgraphs
#define NL   64       // max subgraph size
#define NCLS 10
#define SCAN_BS 512
#define SCAN_NB ((NN + SCAN_BS - 1) / SCAN_BS)

// ---------------- scratch (no allocations allowed -> __device__ globals) ---
__device__ int    g_cnt[NN];       // zeroed at load; re-zeroed per launch in k_scan3
__device__ float  g_dinv[NN];
__device__ int    g_off[NN + 1];
__device__ int    g_cur[NN];
__device__ int    g_bsum[SCAN_NB];
__device__ int    g_csr_src[NE];
__device__ __half g_hw[NN * CF];   // h @ W scratch (fp16: halves gather traffic)
__device__ float  g_h1[NN * CF];   // layer-1 output
__device__ float  g_h2[NN * CF];   // layer-2 output
__device__ int    g_e64;           // edge_index is int64?
__device__ int    g_s64;           // subgraphs is int64?

// ---------------- dtype detection (int64 vs int32, decided on-device) ------
__global__ void k_detect(const unsigned int* __restrict__ ei,
                         const unsigned int* __restrict__ sg) {
    if (threadIdx.x == 0 && blockIdx.x == 0) {
        int e64 = 1;
        for (int i = 0; i < 64; i++)
            if (ei[2 * i + 1] != 0u) { e64 = 0; break; }
        int s64 = 1;
        for (int i = 0; i < 64; i++) {
            unsigned hi = sg[2 * i + 1];
            if (hi != 0u && hi != 0xFFFFFFFFu) { s64 = 0; break; }
        }
        g_e64 = e64;
        g_s64 = s64;
    }
}

__device__ __forceinline__ int load_idx(const void* p, int i, int is64) {
    return is64 ? (int)((const long long*)p)[i] : ((const int*)p)[i];
}

// ---------------- degree count ---------------------------------------------
__global__ void k_count(const void* __restrict__ ei) {
    int e = blockIdx.x * blockDim.x + threadIdx.x;
    if (e >= NE) return;
    int d = load_idx(ei, NE + e, g_e64);   // dst = second row
    atomicAdd(&g_cnt[d], 1);
}

// ---------------- scan1: per-block exclusive scan + dinv -------------------
__global__ void k_scan1() {
    __shared__ int sm[SCAN_BS];
    int gid = blockIdx.x * SCAN_BS + threadIdx.x;
    int v = (gid < NN) ? g_cnt[gid] : 0;
    if (gid < NN) g_dinv[gid] = rsqrtf((float)(v + 1));  // +1 self-loop
    sm[threadIdx.x] = v;
    __syncthreads();
    for (int ofs = 1; ofs < SCAN_BS; ofs <<= 1) {
        int t = (threadIdx.x >= ofs) ? sm[threadIdx.x - ofs] : 0;
        __syncthreads();
        sm[threadIdx.x] += t;
        __syncthreads();
    }
    if (gid < NN) g_off[gid] = sm[threadIdx.x] - v;          // exclusive
    if (threadIdx.x == SCAN_BS - 1) g_bsum[blockIdx.x] = sm[threadIdx.x];
}

// ---------------- scan2: parallel exclusive scan of block sums -------------
__global__ void k_scan2() {
    __shared__ int sm[256];
    int tid = threadIdx.x;
    int v = (tid < SCAN_NB) ? g_bsum[tid] : 0;
    sm[tid] = v;
    __syncthreads();
    for (int ofs = 1; ofs < 256; ofs <<= 1) {
        int t = (tid >= ofs) ? sm[tid - ofs] : 0;
        __syncthreads();
        sm[tid] += t;
        __syncthreads();
    }
    if (tid < SCAN_NB) g_bsum[tid] = sm[tid] - v;            // exclusive
}

// ---------------- scan3: finalize offsets, re-zero counts ------------------
__global__ void k_scan3() {
    int gid = blockIdx.x * SCAN_BS + threadIdx.x;
    if (gid < NN) {
        int o = g_off[gid] + g_bsum[blockIdx.x];
        g_off[gid] = o;
        g_cur[gid] = o;
        g_cnt[gid] = 0;                 // ready for the next graph replay
    }
    if (gid == 0) g_off[NN] = NE;
}

// ---------------- CSR fill (group edges by dst; src only) ------------------
__global__ void k_fill(const void* __restrict__ ei) {
    int e = blockIdx.x * blockDim.x + threadIdx.x;
    if (e >= NE) return;
    int is64 = g_e64;
    int s = load_idx(ei, e, is64);
    int d = load_idx(ei, NE + e, is64);
    int pos = atomicAdd(&g_cur[d], 1);
    g_csr_src[pos] = s;
}

// ---------------- tf32 tensor-core GEMM with hi/lo split -------------------
__device__ __forceinline__ uint32_t f2tf32(float f) {
    uint32_t u;
    asm("cvt.rna.tf32.f32 %0, %1;" : "=r"(u) : "f"(f));
    return u;
}

__device__ __forceinline__ void mma8(float& d0, float& d1, float& d2, float& d3,
                                     uint32_t a0, uint32_t a1, uint32_t a2, uint32_t a3,
                                     uint32_t b0, uint32_t b1) {
    asm volatile(
        "mma.sync.aligned.m16n8k8.row.col.f32.tf32.tf32.f32 "
        "{%0,%1,%2,%3}, {%4,%5,%6,%7}, {%8,%9}, {%0,%1,%2,%3};"
        : "+f"(d0), "+f"(d1), "+f"(d2), "+f"(d3)
        : "r"(a0), "r"(a1), "r"(a2), "r"(a3), "r"(b0), "r"(b1));
}

// O[M,128] = A[M,128] @ W[128,128], split-tf32 (3 MMAs -> ~fp32 accuracy).
// Output stored fp16 into g_hw.
__global__ __launch_bounds__(256) void k_gemm_tc(const float* __restrict__ Aext,
                                                 const float* __restrict__ W,
                                                 int src_sel /*0=Aext 1=g_h1*/) {
    __shared__ uint32_t BsHi[32][136];
    __shared__ uint32_t BsLo[32][136];
    const float* A = src_sel ? g_h1 : Aext;
    __half* O = g_hw;

    int tid = threadIdx.x;
    int wid = tid >> 5, lane = tid & 31;
    int g = lane >> 2, tg = lane & 3;
    int row0 = blockIdx.x * 128 + wid * 16;
    int r0 = row0 + g, r1 = r0 + 8;
    bool v0 = r0 < NN, v1 = r1 < NN;

    float acc[16][4];
#pragma unroll
    for (int nt = 0; nt < 16; nt++)
#pragma unroll
        for (int i = 0; i < 4; i++) acc[nt][i] = 0.f;

    for (int kc = 0; kc < 4; kc++) {
        int k0c = kc * 32;
#pragma unroll
        for (int j = 0; j < 4; j++) {
            int q = tid + j * 256;
            int br = q >> 5, bc = (q & 31) * 4;
            float4 w4 = *(const float4*)&W[(k0c + br) * CF + bc];
            uint32_t h0 = f2tf32(w4.x), h1 = f2tf32(w4.y);
            uint32_t h2 = f2tf32(w4.z), h3 = f2tf32(w4.w);
            BsHi[br][bc + 0] = h0; BsHi[br][bc + 1] = h1;
            BsHi[br][bc + 2] = h2; BsHi[br][bc + 3] = h3;
            BsLo[br][bc + 0] = f2tf32(w4.x - __uint_as_float(h0));
            BsLo[br][bc + 1] = f2tf32(w4.y - __uint_as_float(h1));
            BsLo[br][bc + 2] = f2tf32(w4.z - __uint_as_float(h2));
            BsLo[br][bc + 3] = f2tf32(w4.w - __uint_as_float(h3));
        }
        __syncthreads();
#pragma unroll
        for (int ks = 0; ks < 4; ks++) {
            int kg = k0c + ks * 8;
            float a0 = v0 ? A[r0 * CF + kg + tg] : 0.f;
            float a1 = v1 ? A[r1 * CF + kg + tg] : 0.f;
            float a2 = v0 ? A[r0 * CF + kg + tg + 4] : 0.f;
            float a3 = v1 ? A[r1 * CF + kg + tg + 4] : 0.f;
            uint32_t ah0 = f2tf32(a0), ah1 = f2tf32(a1);
            uint32_t ah2 = f2tf32(a2), ah3 = f2tf32(a3);
            uint32_t al0 = f2tf32(a0 - __uint_as_float(ah0));
            uint32_t al1 = f2tf32(a1 - __uint_as_float(ah1));
            uint32_t al2 = f2tf32(a2 - __uint_as_float(ah2));
            uint32_t al3 = f2tf32(a3 - __uint_as_float(ah3));
            int kb = ks * 8;
#pragma unroll
            for (int nt = 0; nt < 16; nt++) {
                uint32_t bh0 = BsHi[kb + tg][nt * 8 + g];
                uint32_t bh1 = BsHi[kb + tg + 4][nt * 8 + g];
                uint32_t bl0 = BsLo[kb + tg][nt * 8 + g];
                uint32_t bl1 = BsLo[kb + tg + 4][nt * 8 + g];
                mma8(acc[nt][0], acc[nt][1], acc[nt][2], acc[nt][3],
                     ah0, ah1, ah2, ah3, bh0, bh1);
                mma8(acc[nt][0], acc[nt][1], acc[nt][2], acc[nt][3],
                     al0, al1, al2, al3, bh0, bh1);
                mma8(acc[nt][0], acc[nt][1], acc[nt][2], acc[nt][3],
                     ah0, ah1, ah2, ah3, bl0, bl1);
            }
        }
        __syncthreads();
    }
#pragma unroll
    for (int nt = 0; nt < 16; nt++) {
        int c = nt * 8 + tg * 2;
        if (v0) *(__half2*)&O[r0 * CF + c] = __floats2half2_rn(acc[nt][0], acc[nt][1]);
        if (v1) *(__half2*)&O[r1 * CF + c] = __floats2half2_rn(acc[nt][2], acc[nt][3]);
    }
}

// ---------------- aggregation ----------------------------------------------
// One warp per node; 16 lanes cover the 128-ch row (8 halves / lane, uint4
// load), two edges in flight per warp iteration (half = lane>>4 picks edge).
// Weight recomputed as dinv[src]*dinv[dst] (broadcast loads, L1/L2-hot).
__device__ __forceinline__ void acc8(float2& a0, float2& a1, float2& a2, float2& a3,
                                     uint4 u, float w) {
    float2 f0 = __half22float2(*reinterpret_cast<__half2*>(&u.x));
    float2 f1 = __half22float2(*reinterpret_cast<__half2*>(&u.y));
    float2 f2 = __half22float2(*reinterpret_cast<__half2*>(&u.z));
    float2 f3 = __half22float2(*reinterpret_cast<__half2*>(&u.w));
    a0.x = fmaf(f0.x, w, a0.x); a0.y = fmaf(f0.y, w, a0.y);
    a1.x = fmaf(f1.x, w, a1.x); a1.y = fmaf(f1.y, w, a1.y);
    a2.x = fmaf(f2.x, w, a2.x); a2.y = fmaf(f2.y, w, a2.y);
    a3.x = fmaf(f3.x, w, a3.x); a3.y = fmaf(f3.y, w, a3.y);
}

__global__ __launch_bounds__(256) void k_agg(const float* __restrict__ bias,
                                             int dst_sel /*1=g_h1 2=g_h2*/,
                                             int do_relu) {
    int gw = (blockIdx.x * blockDim.x + threadIdx.x) >> 5;
    int lane = threadIdx.x & 31;
    if (gw >= NN) return;
    int half = lane >> 4, hl = lane & 15;
    const __half* hw = g_hw;
    float* out = (dst_sel == 1) ? g_h1 : g_h2;

    float di = g_dinv[gw];
    float2 a0 = {0.f, 0.f}, a1 = {0.f, 0.f}, a2 = {0.f, 0.f}, a3 = {0.f, 0.f};

    if (half == 0) {   // self-loop term, counted once
        uint4 u = *(const uint4*)&hw[gw * CF + hl * 8];
        acc8(a0, a1, a2, a3, u, di * di);
    }

    int e = g_off[gw] + half, e1 = g_off[gw + 1];
    for (; e + 2 < e1; e += 4) {   // two edges per half-warp per iter
        int sA = g_csr_src[e], sB = g_csr_src[e + 2];
        float wA = g_dinv[sA] * di, wB = g_dinv[sB] * di;
        uint4 uA = *(const uint4*)&hw[sA * CF + hl * 8];
        uint4 uB = *(const uint4*)&hw[sB * CF + hl * 8];
        acc8(a0, a1, a2, a3, uA, wA);
        acc8(a0, a1, a2, a3, uB, wB);
    }
    if (e < e1) {
        int sA = g_csr_src[e];
        float wA = g_dinv[sA] * di;
        uint4 uA = *(const uint4*)&hw[sA * CF + hl * 8];
        acc8(a0, a1, a2, a3, uA, wA);
    }

    // combine the two half-warps (same channels)
    a0.x += __shfl_down_sync(0xffffffffu, a0.x, 16);
    a0.y += __shfl_down_sync(0xffffffffu, a0.y, 16);
    a1.x += __shfl_down_sync(0xffffffffu, a1.x, 16);
    a1.y += __shfl_down_sync(0xffffffffu, a1.y, 16);
    a2.x += __shfl_down_sync(0xffffffffu, a2.x, 16);
    a2.y += __shfl_down_sync(0xffffffffu, a2.y, 16);
    a3.x += __shfl_down_sync(0xffffffffu, a3.x, 16);
    a3.y += __shfl_down_sync(0xffffffffu, a3.y, 16);

    if (half == 0) {
        float4 b0 = *(const float4*)&bias[hl * 8];
        float4 b1 = *(const float4*)&bias[hl * 8 + 4];
        float r0 = a0.x + b0.x, r1 = a0.y + b0.y;
        float r2 = a1.x + b0.z, r3 = a1.y + b0.w;
        float r4 = a2.x + b1.x, r5 = a2.y + b1.y;
        float r6 = a3.x + b1.z, r7 = a3.y + b1.w;
        if (do_relu) {
            r0 = fmaxf(r0, 0.f); r1 = fmaxf(r1, 0.f);
            r2 = fmaxf(r2, 0.f); r3 = fmaxf(r3, 0.f);
            r4 = fmaxf(r4, 0.f); r5 = fmaxf(r5, 0.f);
            r6 = fmaxf(r6, 0.f); r7 = fmaxf(r7, 0.f);
        }
        *(float4*)&out[gw * CF + hl * 8]     = make_float4(r0, r1, r2, r3);
        *(float4*)&out[gw * CF + hl * 8 + 4] = make_float4(r4, r5, r6, r7);
    }
}

// ---------------- subgraph mean-pool + classifier --------------------------
__global__ __launch_bounds__(256) void k_pool(const void* __restrict__ sg,
                                              const float* __restrict__ Wc,
                                              const float* __restrict__ bc,
                                              float* __restrict__ out) {
    int gw = (blockIdx.x * blockDim.x + threadIdx.x) >> 5;
    int lane = threadIdx.x & 31;
    if (gw >= NS) return;
    int is64 = g_s64;

    float ax = 0.f, ay = 0.f, az = 0.f, aw = 0.f;
    int cnt = 0;
    for (int l = 0; l < NL; l++) {
        int idx = load_idx(sg, gw * NL + l, is64);
        if (idx >= 0) {
            cnt++;
            float4 v = *(const float4*)&g_h2[idx * CF + lane * 4];
            ax += v.x; ay += v.y; az += v.z; aw += v.w;
        }
    }
    float inv = 1.0f / (float)(cnt > 0 ? cnt : 1);
    ax *= inv; ay *= inv; az *= inv; aw *= inv;

    float res[NCLS];
#pragma unroll
    for (int c = 0; c < NCLS; c++) {
        int k = lane * 4;
        res[c] = ax * Wc[(k + 0) * NCLS + c] + ay * Wc[(k + 1) * NCLS + c] +
                 az * Wc[(k + 2) * NCLS + c] + aw * Wc[(k + 3) * NCLS + c];
    }
#pragma unroll
    for (int c = 0; c < NCLS; c++) {
        float v = res[c];
#pragma unroll
        for (int o = 16; o > 0; o >>= 1) v += __shfl_xor_sync(0xffffffffu, v, o);
        if (lane == 0) out[gw * NCLS + c] = v + bc[c];
    }
}

// ---------------- launch ----------------------------------------------------
extern "C" void kernel_launch(void* const* d_in, const int* in_sizes, int n_in,
                              void* d_out, int out_size) {
    const float* x  = (const float*)d_in[0];   // (N,1,128) contiguous
    const void*  ei = d_in[1];                 // (2,E) int64 or int32
    const void*  sg = d_in[2];                 // (S,64) int64 or int32
    const float* W1 = (const float*)d_in[3];
    const float* b1 = (const float*)d_in[4];
    const float* W2 = (const float*)d_in[5];
    const float* b2 = (const float*)d_in[6];
    const float* Wc = (const float*)d_in[7];
    const float* bc = (const float*)d_in[8];
    float* out = (float*)d_out;

    const int TB = 256;
    const int nbE = (NE + TB - 1) / TB;
    const int nbG = (NN + 127) / 128;
    const int nbA = (NN * 32 + TB - 1) / TB;   // warp per node
    const int nbP = (NS * 32 + TB - 1) / TB;   // warp per subgraph

    // GEMM1 placed 4th: the profiler samples the 4th launch -> useful profile.
    k_detect<<<1, 32>>>((const unsigned int*)ei, (const unsigned int*)sg);
    k_count<<<nbE, TB>>>(ei);                  // g_cnt pre-zeroed (init / k_scan3)
    k_scan1<<<SCAN_NB, SCAN_BS>>>();
    k_gemm_tc<<<nbG, TB>>>(x, W1, 0);          // hw = x @ W1 (fp16 out)
    k_scan2<<<1, 256>>>();
    k_scan3<<<SCAN_NB, SCAN_BS>>>();
    k_fill<<<nbE, TB>>>(ei);

    k_agg<<<nbA, TB>>>(b1, 1, 1);              // h1 = relu(agg(hw) + b1)
    k_gemm_tc<<<nbG, TB>>>(x, W2, 1);          // hw = h1 @ W2 (fp16 out)
    k_agg<<<nbA, TB>>>(b2, 2, 0);              // h2 = agg(hw) + b2
    k_pool<<<nbP, TB>>>(sg, Wc, bc, out);
}

// round 4
// speedup vs baseline: 1.8103x; 1.3664x over previous
#include <cuda_runtime.h>
#include <cuda_fp16.h>
#include <cstdint>

#define NN   100000   // nodes
#define CF   128      // feature dim (C_in == H == 128)
#define NE   1600000  // edges
#define NS   4096     // subgraphs
#define NL   64       // max subgraph size
#define NCLS 10
#define SCAN_BS 512
#define SCAN_NB ((NN + SCAN_BS - 1) / SCAN_BS)

// ---------------- scratch (no allocations allowed -> __device__ globals) ---
__device__ int    g_cnt[NN];       // zeroed at load; re-zeroed per launch in k_scan3
__device__ float  g_dinv[NN];
__device__ int    g_off[NN + 1];
__device__ int    g_cur[NN];
__device__ int    g_bsum[SCAN_NB];
__device__ int    g_csr_src[NE];
__device__ __half g_hw[NN * CF];   // h @ W scratch (fp16)
__device__ float  g_h1[NN * CF];   // layer-1 output (fp32: feeds GEMM2)
__device__ __half g_h2h[NN * CF];  // layer-2 output (fp16: feeds pool only)
__device__ int    g_e64;           // edge_index is int64?
__device__ int    g_s64;           // subgraphs is int64?

// ---------------- dtype detection (int64 vs int32, decided on-device) ------
__global__ void k_detect(const unsigned int* __restrict__ ei,
                         const unsigned int* __restrict__ sg) {
    if (threadIdx.x == 0 && blockIdx.x == 0) {
        int e64 = 1;
        for (int i = 0; i < 64; i++)
            if (ei[2 * i + 1] != 0u) { e64 = 0; break; }
        int s64 = 1;
        for (int i = 0; i < 64; i++) {
            unsigned hi = sg[2 * i + 1];
            if (hi != 0u && hi != 0xFFFFFFFFu) { s64 = 0; break; }
        }
        g_e64 = e64;
        g_s64 = s64;
    }
}

__device__ __forceinline__ int load_idx(const void* p, int i, int is64) {
    return is64 ? (int)((const long long*)p)[i] : ((const int*)p)[i];
}

// ---------------- degree count ---------------------------------------------
__global__ void k_count(const void* __restrict__ ei) {
    int e = blockIdx.x * blockDim.x + threadIdx.x;
    if (e >= NE) return;
    int d = load_idx(ei, NE + e, g_e64);   // dst = second row
    atomicAdd(&g_cnt[d], 1);
}

// ---------------- scan1: per-block exclusive scan + dinv -------------------
__global__ void k_scan1() {
    __shared__ int sm[SCAN_BS];
    int gid = blockIdx.x * SCAN_BS + threadIdx.x;
    int v = (gid < NN) ? g_cnt[gid] : 0;
    if (gid < NN) g_dinv[gid] = rsqrtf((float)(v + 1));  // +1 self-loop
    sm[threadIdx.x] = v;
    __syncthreads();
    for (int ofs = 1; ofs < SCAN_BS; ofs <<= 1) {
        int t = (threadIdx.x >= ofs) ? sm[threadIdx.x - ofs] : 0;
        __syncthreads();
        sm[threadIdx.x] += t;
        __syncthreads();
    }
    if (gid < NN) g_off[gid] = sm[threadIdx.x] - v;          // exclusive
    if (threadIdx.x == SCAN_BS - 1) g_bsum[blockIdx.x] = sm[threadIdx.x];
}

// ---------------- scan2: parallel exclusive scan of block sums -------------
__global__ void k_scan2() {
    __shared__ int sm[256];
    int tid = threadIdx.x;
    int v = (tid < SCAN_NB) ? g_bsum[tid] : 0;
    sm[tid] = v;
    __syncthreads();
    for (int ofs = 1; ofs < 256; ofs <<= 1) {
        int t = (tid >= ofs) ? sm[tid - ofs] : 0;
        __syncthreads();
        sm[tid] += t;
        __syncthreads();
    }
    if (tid < SCAN_NB) g_bsum[tid] = sm[tid] - v;            // exclusive
}

// ---------------- scan3: finalize offsets, re-zero counts ------------------
__global__ void k_scan3() {
    int gid = blockIdx.x * SCAN_BS + threadIdx.x;
    if (gid < NN) {
        int o = g_off[gid] + g_bsum[blockIdx.x];
        g_off[gid] = o;
        g_cur[gid] = o;
        g_cnt[gid] = 0;                 // ready for the next graph replay
    }
    if (gid == 0) g_off[NN] = NE;
}

// ---------------- CSR fill (group edges by dst; src only) ------------------
__global__ void k_fill(const void* __restrict__ ei) {
    int e = blockIdx.x * blockDim.x + threadIdx.x;
    if (e >= NE) return;
    int is64 = g_e64;
    int s = load_idx(ei, e, is64);
    int d = load_idx(ei, NE + e, is64);
    int pos = atomicAdd(&g_cur[d], 1);
    g_csr_src[pos] = s;
}

// ---------------- split-fp16 tensor-core GEMM ------------------------------
__device__ __forceinline__ void ldsm_x4(uint32_t& r0, uint32_t& r1,
                                        uint32_t& r2, uint32_t& r3, uint32_t a) {
    asm volatile("ldmatrix.sync.aligned.m8n8.x4.shared.b16 {%0,%1,%2,%3}, [%4];"
                 : "=r"(r0), "=r"(r1), "=r"(r2), "=r"(r3) : "r"(a));
}
__device__ __forceinline__ void ldsm_x4_t(uint32_t& r0, uint32_t& r1,
                                          uint32_t& r2, uint32_t& r3, uint32_t a) {
    asm volatile("ldmatrix.sync.aligned.m8n8.x4.trans.shared.b16 {%0,%1,%2,%3}, [%4];"
                 : "=r"(r0), "=r"(r1), "=r"(r2), "=r"(r3) : "r"(a));
}
__device__ __forceinline__ void mma16(float* d, const uint32_t* a,
                                      uint32_t b0, uint32_t b1) {
    asm volatile(
        "mma.sync.aligned.m16n8k16.row.col.f32.f16.f16.f32 "
        "{%0,%1,%2,%3}, {%4,%5,%6,%7}, {%8,%9}, {%0,%1,%2,%3};"
        : "+f"(d[0]), "+f"(d[1]), "+f"(d[2]), "+f"(d[3])
        : "r"(a[0]), "r"(a[1]), "r"(a[2]), "r"(a[3]), "r"(b0), "r"(b1));
}
__device__ __forceinline__ void cvt_hilo(float4 v, uint2& hi, uint2& lo) {
    __half2 h01 = __floats2half2_rn(v.x, v.y);
    __half2 h23 = __floats2half2_rn(v.z, v.w);
    float2 f01 = __half22float2(h01);
    float2 f23 = __half22float2(h23);
    __half2 l01 = __floats2half2_rn(v.x - f01.x, v.y - f01.y);
    __half2 l23 = __floats2half2_rn(v.z - f23.x, v.w - f23.y);
    hi.x = *(uint32_t*)&h01; hi.y = *(uint32_t*)&h23;
    lo.x = *(uint32_t*)&l01; lo.y = *(uint32_t*)&l23;
}

// O[M,128] = A[M,128] @ W[128,128]; hi/lo fp16 split, 3 MMAs per k16 step
// (AhBh + AlBh + AhBl -> ~2^-21 rel accuracy). Output fp16 into g_hw.
// Block: 256 thr = 8 warps; block tile 128x128; warp tile 32 rows x 64 cols.
// A smem [128][40] halves (stride 40 -> ldmatrix banks 20r%32 all-distinct);
// W smem [32][136] halves (stride 136 -> trans-ldmatrix banks 4k%32 distinct).
__global__ __launch_bounds__(256) void k_gemm_tc(const float* __restrict__ Aext,
                                                 const float* __restrict__ W,
                                                 int src_sel /*0=Aext 1=g_h1*/) {
    __shared__ __half AsHi[128][40], AsLo[128][40];
    __shared__ __half WsHi[32][136], WsLo[32][136];
    const float* A = src_sel ? g_h1 : Aext;
    __half* O = g_hw;

    int tid = threadIdx.x;
    int wid = tid >> 5, lane = tid & 31;
    int mrow = (wid >> 1) * 32;          // warp row offset in tile
    int ncol0 = (wid & 1) * 64;          // warp col offset (8 n-tiles of 8)
    int row0 = blockIdx.x * 128;

    uint32_t sAhi = (uint32_t)__cvta_generic_to_shared(&AsHi[0][0]);
    uint32_t sAlo = (uint32_t)__cvta_generic_to_shared(&AsLo[0][0]);
    uint32_t sWhi = (uint32_t)__cvta_generic_to_shared(&WsHi[0][0]);
    uint32_t sWlo = (uint32_t)__cvta_generic_to_shared(&WsLo[0][0]);

    float acc[2][8][4];
#pragma unroll
    for (int mb = 0; mb < 2; mb++)
#pragma unroll
        for (int nt = 0; nt < 8; nt++)
#pragma unroll
            for (int i = 0; i < 4; i++) acc[mb][nt][i] = 0.f;

    for (int kc = 0; kc < 4; kc++) {
        // stage A chunk [128 rows][32 k] (coalesced float4)
#pragma unroll
        for (int j = 0; j < 4; j++) {
            int q = tid + j * 256;
            int row = q >> 3, cg = q & 7;
            int gr = row0 + row;
            float4 v = make_float4(0.f, 0.f, 0.f, 0.f);
            if (gr < NN) v = *(const float4*)&A[gr * CF + kc * 32 + cg * 4];
            uint2 hi, lo;
            cvt_hilo(v, hi, lo);
            *(uint2*)&AsHi[row][cg * 4] = hi;
            *(uint2*)&AsLo[row][cg * 4] = lo;
        }
        // stage W chunk [32 k][128 n]
#pragma unroll
        for (int j = 0; j < 4; j++) {
            int q = tid + j * 256;
            int br = q >> 5, bc = (q & 31) * 4;
            float4 v = *(const float4*)&W[(kc * 32 + br) * CF + bc];
            uint2 hi, lo;
            cvt_hilo(v, hi, lo);
            *(uint2*)&WsHi[br][bc] = hi;
            *(uint2*)&WsLo[br][bc] = lo;
        }
        __syncthreads();

#pragma unroll
        for (int ks = 0; ks < 2; ks++) {
            int kb = ks * 16;
            // A fragments: ldmatrix x4 (a0..a3), hi and lo, 2 m-blocks
            uint32_t ah[2][4], al[2][4];
            int arow = mrow + (lane & 15);
            int acol = kb + ((lane & 16) >> 1);  // +8 for lanes 16-31
#pragma unroll
            for (int mb = 0; mb < 2; mb++) {
                uint32_t off = (uint32_t)(((arow + mb * 16) * 40 + acol) * 2);
                ldsm_x4(ah[mb][0], ah[mb][1], ah[mb][2], ah[mb][3], sAhi + off);
                ldsm_x4(al[mb][0], al[mb][1], al[mb][2], al[mb][3], sAlo + off);
            }
            // B fragments: trans ldmatrix x4 covers 2 n-tiles (b0,b1 each)
            int krow = kb + (lane & 7) + (lane & 8);
            int ncol = ncol0 + ((lane & 16) >> 1);
#pragma unroll
            for (int p = 0; p < 4; p++) {
                uint32_t off = (uint32_t)((krow * 136 + ncol + p * 16) * 2);
                uint32_t bh0, bh1, bh2, bh3, bl0, bl1, bl2, bl3;
                ldsm_x4_t(bh0, bh1, bh2, bh3, sWhi + off);
                ldsm_x4_t(bl0, bl1, bl2, bl3, sWlo + off);
#pragma unroll
                for (int mb = 0; mb < 2; mb++) {
                    mma16(acc[mb][2 * p], ah[mb], bh0, bh1);
                    mma16(acc[mb][2 * p], al[mb], bh0, bh1);
                    mma16(acc[mb][2 * p], ah[mb], bl0, bl1);
                    mma16(acc[mb][2 * p + 1], ah[mb], bh2, bh3);
                    mma16(acc[mb][2 * p + 1], al[mb], bh2, bh3);
                    mma16(acc[mb][2 * p + 1], ah[mb], bl2, bl3);
                }
            }
        }
        __syncthreads();
    }

    int g = lane >> 2, tg = lane & 3;
#pragma unroll
    for (int mb = 0; mb < 2; mb++) {
#pragma unroll
        for (int nt = 0; nt < 8; nt++) {
            int r = row0 + mrow + mb * 16 + g;
            int c = ncol0 + nt * 8 + tg * 2;
            if (r < NN)
                *(__half2*)&O[r * CF + c] =
                    __floats2half2_rn(acc[mb][nt][0], acc[mb][nt][1]);
            if (r + 8 < NN)
                *(__half2*)&O[(r + 8) * CF + c] =
                    __floats2half2_rn(acc[mb][nt][2], acc[mb][nt][3]);
        }
    }
}

// ---------------- aggregation ----------------------------------------------
__device__ __forceinline__ void acc8(float2& a0, float2& a1, float2& a2, float2& a3,
                                     uint4 u, float w) {
    float2 f0 = __half22float2(*reinterpret_cast<__half2*>(&u.x));
    float2 f1 = __half22float2(*reinterpret_cast<__half2*>(&u.y));
    float2 f2 = __half22float2(*reinterpret_cast<__half2*>(&u.z));
    float2 f3 = __half22float2(*reinterpret_cast<__half2*>(&u.w));
    a0.x = fmaf(f0.x, w, a0.x); a0.y = fmaf(f0.y, w, a0.y);
    a1.x = fmaf(f1.x, w, a1.x); a1.y = fmaf(f1.y, w, a1.y);
    a2.x = fmaf(f2.x, w, a2.x); a2.y = fmaf(f2.y, w, a2.y);
    a3.x = fmaf(f3.x, w, a3.x); a3.y = fmaf(f3.y, w, a3.y);
}

__global__ __launch_bounds__(256) void k_agg(const float* __restrict__ bias,
                                             int dst_sel /*1=g_h1(f32) 2=g_h2h(f16)*/,
                                             int do_relu) {
    int gw = (blockIdx.x * blockDim.x + threadIdx.x) >> 5;
    int lane = threadIdx.x & 31;
    if (gw >= NN) return;
    int half = lane >> 4, hl = lane & 15;
    const __half* hw = g_hw;

    float di = g_dinv[gw];
    float2 a0 = {0.f, 0.f}, a1 = {0.f, 0.f}, a2 = {0.f, 0.f}, a3 = {0.f, 0.f};

    if (half == 0) {   // self-loop term, counted once
        uint4 u = *(const uint4*)&hw[gw * CF + hl * 8];
        acc8(a0, a1, a2, a3, u, di * di);
    }

    int e = g_off[gw] + half, e1 = g_off[gw + 1];
    for (; e + 2 < e1; e += 4) {   // two edges per half-warp per iter
        int sA = g_csr_src[e], sB = g_csr_src[e + 2];
        float wA = g_dinv[sA] * di, wB = g_dinv[sB] * di;
        uint4 uA = *(const uint4*)&hw[sA * CF + hl * 8];
        uint4 uB = *(const uint4*)&hw[sB * CF + hl * 8];
        acc8(a0, a1, a2, a3, uA, wA);
        acc8(a0, a1, a2, a3, uB, wB);
    }
    if (e < e1) {
        int sA = g_csr_src[e];
        float wA = g_dinv[sA] * di;
        uint4 uA = *(const uint4*)&hw[sA * CF + hl * 8];
        acc8(a0, a1, a2, a3, uA, wA);
    }

    a0.x += __shfl_down_sync(0xffffffffu, a0.x, 16);
    a0.y += __shfl_down_sync(0xffffffffu, a0.y, 16);
    a1.x += __shfl_down_sync(0xffffffffu, a1.x, 16);
    a1.y += __shfl_down_sync(0xffffffffu, a1.y, 16);
    a2.x += __shfl_down_sync(0xffffffffu, a2.x, 16);
    a2.y += __shfl_down_sync(0xffffffffu, a2.y, 16);
    a3.x += __shfl_down_sync(0xffffffffu, a3.x, 16);
    a3.y += __shfl_down_sync(0xffffffffu, a3.y, 16);

    if (half == 0) {
        float4 b0 = *(const float4*)&bias[hl * 8];
        float4 b1 = *(const float4*)&bias[hl * 8 + 4];
        float r0 = a0.x + b0.x, r1 = a0.y + b0.y;
        float r2 = a1.x + b0.z, r3 = a1.y + b0.w;
        float r4 = a2.x + b1.x, r5 = a2.y + b1.y;
        float r6 = a3.x + b1.z, r7 = a3.y + b1.w;
        if (do_relu) {
            r0 = fmaxf(r0, 0.f); r1 = fmaxf(r1, 0.f);
            r2 = fmaxf(r2, 0.f); r3 = fmaxf(r3, 0.f);
            r4 = fmaxf(r4, 0.f); r5 = fmaxf(r5, 0.f);
            r6 = fmaxf(r6, 0.f); r7 = fmaxf(r7, 0.f);
        }
        if (dst_sel == 1) {
            *(float4*)&g_h1[gw * CF + hl * 8]     = make_float4(r0, r1, r2, r3);
            *(float4*)&g_h1[gw * CF + hl * 8 + 4] = make_float4(r4, r5, r6, r7);
        } else {
            __half2 p0 = __floats2half2_rn(r0, r1);
            __half2 p1 = __floats2half2_rn(r2, r3);
            __half2 p2 = __floats2half2_rn(r4, r5);
            __half2 p3 = __floats2half2_rn(r6, r7);
            uint4 u;
            u.x = *(uint32_t*)&p0; u.y = *(uint32_t*)&p1;
            u.z = *(uint32_t*)&p2; u.w = *(uint32_t*)&p3;
            *(uint4*)&g_h2h[gw * CF + hl * 8] = u;
        }
    }
}

// ---------------- subgraph mean-pool + classifier (fp16 h2) ----------------
__global__ __launch_bounds__(256) void k_pool(const void* __restrict__ sg,
                                              const float* __restrict__ Wc,
                                              const float* __restrict__ bc,
                                              float* __restrict__ out) {
    int gw = (blockIdx.x * blockDim.x + threadIdx.x) >> 5;
    int lane = threadIdx.x & 31;
    if (gw >= NS) return;
    int is64 = g_s64;
    int half = lane >> 4, hl = lane & 15;

    float a[8];
#pragma unroll
    for (int i = 0; i < 8; i++) a[i] = 0.f;
    int cnt = 0;
    for (int l = half; l < NL; l += 2) {
        int idx = load_idx(sg, gw * NL + l, is64);
        if (idx >= 0) {
            cnt++;
            uint4 u = *(const uint4*)&g_h2h[idx * CF + hl * 8];
            float2 f0 = __half22float2(*reinterpret_cast<__half2*>(&u.x));
            float2 f1 = __half22float2(*reinterpret_cast<__half2*>(&u.y));
            float2 f2 = __half22float2(*reinterpret_cast<__half2*>(&u.z));
            float2 f3 = __half22float2(*reinterpret_cast<__half2*>(&u.w));
            a[0] += f0.x; a[1] += f0.y; a[2] += f1.x; a[3] += f1.y;
            a[4] += f2.x; a[5] += f2.y; a[6] += f3.x; a[7] += f3.y;
        }
    }
#pragma unroll
    for (int i = 0; i < 8; i++)
        a[i] += __shfl_down_sync(0xffffffffu, a[i], 16);
    cnt += __shfl_down_sync(0xffffffffu, cnt, 16);

    float inv = 1.0f / (float)(cnt > 0 ? cnt : 1);
#pragma unroll
    for (int i = 0; i < 8; i++) a[i] *= inv;

    float res[NCLS];
#pragma unroll
    for (int c = 0; c < NCLS; c++) {
        float v = 0.f;
#pragma unroll
        for (int i = 0; i < 8; i++) v += a[i] * Wc[(hl * 8 + i) * NCLS + c];
        res[c] = v;
    }
#pragma unroll
    for (int c = 0; c < NCLS; c++) {
        float v = res[c];
#pragma unroll
        for (int o = 8; o > 0; o >>= 1) v += __shfl_xor_sync(0xffffffffu, v, o);
        if (lane == 0) out[gw * NCLS + c] = v + bc[c];
    }
}

// ---------------- launch ----------------------------------------------------
extern "C" void kernel_launch(void* const* d_in, const int* in_sizes, int n_in,
                              void* d_out, int out_size) {
    const float* x  = (const float*)d_in[0];   // (N,1,128) contiguous
    const void*  ei = d_in[1];                 // (2,E) int64 or int32
    const void*  sg = d_in[2];                 // (S,64) int64 or int32
    const float* W1 = (const float*)d_in[3];
    const float* b1 = (const float*)d_in[4];
    const float* W2 = (const float*)d_in[5];
    const float* b2 = (const float*)d_in[6];
    const float* Wc = (const float*)d_in[7];
    const float* bc = (const float*)d_in[8];
    float* out = (float*)d_out;

    const int TB = 256;
    const int nbE = (NE + TB - 1) / TB;
    const int nbG = (NN + 127) / 128;
    const int nbA = (NN * 32 + TB - 1) / TB;   // warp per node
    const int nbP = (NS * 32 + TB - 1) / TB;   // warp per subgraph

    // GEMM1 placed 4th: the profiler samples the 4th launch -> useful profile.
    k_detect<<<1, 32>>>((const unsigned int*)ei, (const unsigned int*)sg);
    k_count<<<nbE, TB>>>(ei);                  // g_cnt pre-zeroed (init / k_scan3)
    k_scan1<<<SCAN_NB, SCAN_BS>>>();
    k_gemm_tc<<<nbG, TB>>>(x, W1, 0);          // hw = x @ W1 (fp16 out)
    k_scan2<<<1, 256>>>();
    k_scan3<<<SCAN_NB, SCAN_BS>>>();
    k_fill<<<nbE, TB>>>(ei);

    k_agg<<<nbA, TB>>>(b1, 1, 1);              // h1 = relu(agg(hw) + b1)  (f32)
    k_gemm_tc<<<nbG, TB>>>(x, W2, 1);          // hw = h1 @ W2 (fp16 out)
    k_agg<<<nbA, TB>>>(b2, 2, 0);              // h2 = agg(hw) + b2        (f16)
    k_pool<<<nbP, TB>>>(sg, Wc, bc, out);
}

// round 5
// speedup vs baseline: 1.8247x; 1.0079x over previous
#include <cuda_runtime.h>
#include <cuda_fp16.h>
#include <cstdint>

#define NN   100000   // nodes
#define CF   128      // feature dim (C_in == H == 128)
#define NE   1600000  // edges
#define NS   4096     // subgraphs
#define NL   64       // max subgraph size
#define NCLS 10
#define SCAN_BS 512
#define SCAN_NB ((NN + SCAN_BS - 1) / SCAN_BS)

// ---------------- scratch (no allocations allowed -> __device__ globals) ---
__device__ int    g_cnt[NN];       // zeroed at load; re-zeroed per launch in k_scan3
__device__ float  g_dinv[NN];
__device__ int    g_off[NN + 1];
__device__ int    g_cur[NN];
__device__ int    g_bsum[SCAN_NB];
__device__ int    g_csr_src[NE];
__device__ __half g_hw[NN * CF];   // h @ W scratch (fp16)
__device__ float  g_h1[NN * CF];   // layer-1 output (fp32: feeds GEMM2)
__device__ __half g_h2h[NN * CF];  // layer-2 output (fp16: feeds pool only)
__device__ int    g_e64;           // edge_index is int64?
__device__ int    g_s64;           // subgraphs is int64?

// ---------------- dtype detection (int64 vs int32, decided on-device) ------
__global__ void k_detect(const unsigned int* __restrict__ ei,
                         const unsigned int* __restrict__ sg) {
    if (threadIdx.x == 0 && blockIdx.x == 0) {
        int e64 = 1;
        for (int i = 0; i < 64; i++)
            if (ei[2 * i + 1] != 0u) { e64 = 0; break; }
        int s64 = 1;
        for (int i = 0; i < 64; i++) {
            unsigned hi = sg[2 * i + 1];
            if (hi != 0u && hi != 0xFFFFFFFFu) { s64 = 0; break; }
        }
        g_e64 = e64;
        g_s64 = s64;
    }
}

__device__ __forceinline__ int load_idx(const void* p, int i, int is64) {
    return is64 ? (int)((const long long*)p)[i] : ((const int*)p)[i];
}

// ---------------- degree count ---------------------------------------------
__global__ void k_count(const void* __restrict__ ei) {
    int e = blockIdx.x * blockDim.x + threadIdx.x;
    if (e >= NE) return;
    int d = load_idx(ei, NE + e, g_e64);   // dst = second row
    atomicAdd(&g_cnt[d], 1);
}

// ---------------- scan1: per-block exclusive scan + dinv -------------------
__global__ void k_scan1() {
    __shared__ int sm[SCAN_BS];
    int gid = blockIdx.x * SCAN_BS + threadIdx.x;
    int v = (gid < NN) ? g_cnt[gid] : 0;
    if (gid < NN) g_dinv[gid] = rsqrtf((float)(v + 1));  // +1 self-loop
    sm[threadIdx.x] = v;
    __syncthreads();
    for (int ofs = 1; ofs < SCAN_BS; ofs <<= 1) {
        int t = (threadIdx.x >= ofs) ? sm[threadIdx.x - ofs] : 0;
        __syncthreads();
        sm[threadIdx.x] += t;
        __syncthreads();
    }
    if (gid < NN) g_off[gid] = sm[threadIdx.x] - v;          // exclusive
    if (threadIdx.x == SCAN_BS - 1) g_bsum[blockIdx.x] = sm[threadIdx.x];
}

// ---------------- scan2: parallel exclusive scan of block sums -------------
__global__ void k_scan2() {
    __shared__ int sm[256];
    int tid = threadIdx.x;
    int v = (tid < SCAN_NB) ? g_bsum[tid] : 0;
    sm[tid] = v;
    __syncthreads();
    for (int ofs = 1; ofs < 256; ofs <<= 1) {
        int t = (tid >= ofs) ? sm[tid - ofs] : 0;
        __syncthreads();
        sm[tid] += t;
        __syncthreads();
    }
    if (tid < SCAN_NB) g_bsum[tid] = sm[tid] - v;            // exclusive
}

// ---------------- scan3: finalize offsets, re-zero counts ------------------
__global__ void k_scan3() {
    int gid = blockIdx.x * SCAN_BS + threadIdx.x;
    if (gid < NN) {
        int o = g_off[gid] + g_bsum[blockIdx.x];
        g_off[gid] = o;
        g_cur[gid] = o;
        g_cnt[gid] = 0;                 // ready for the next graph replay
    }
    if (gid == 0) g_off[NN] = NE;
}

// ---------------- CSR fill (group edges by dst; src only) ------------------
__global__ void k_fill(const void* __restrict__ ei) {
    int e = blockIdx.x * blockDim.x + threadIdx.x;
    if (e >= NE) return;
    int is64 = g_e64;
    int s = load_idx(ei, e, is64);
    int d = load_idx(ei, NE + e, is64);
    int pos = atomicAdd(&g_cur[d], 1);
    g_csr_src[pos] = s;
}

// ---------------- split-fp16 tensor-core GEMM ------------------------------
__device__ __forceinline__ void ldsm_x4(uint32_t& r0, uint32_t& r1,
                                        uint32_t& r2, uint32_t& r3, uint32_t a) {
    asm volatile("ldmatrix.sync.aligned.m8n8.x4.shared.b16 {%0,%1,%2,%3}, [%4];"
                 : "=r"(r0), "=r"(r1), "=r"(r2), "=r"(r3) : "r"(a));
}
__device__ __forceinline__ void ldsm_x4_t(uint32_t& r0, uint32_t& r1,
                                          uint32_t& r2, uint32_t& r3, uint32_t a) {
    asm volatile("ldmatrix.sync.aligned.m8n8.x4.trans.shared.b16 {%0,%1,%2,%3}, [%4];"
                 : "=r"(r0), "=r"(r1), "=r"(r2), "=r"(r3) : "r"(a));
}
__device__ __forceinline__ void mma16(float* d, const uint32_t* a,
                                      uint32_t b0, uint32_t b1) {
    asm volatile(
        "mma.sync.aligned.m16n8k16.row.col.f32.f16.f16.f32 "
        "{%0,%1,%2,%3}, {%4,%5,%6,%7}, {%8,%9}, {%0,%1,%2,%3};"
        : "+f"(d[0]), "+f"(d[1]), "+f"(d[2]), "+f"(d[3])
        : "r"(a[0]), "r"(a[1]), "r"(a[2]), "r"(a[3]), "r"(b0), "r"(b1));
}
__device__ __forceinline__ void cvt_hilo(float4 v, uint2& hi, uint2& lo) {
    __half2 h01 = __floats2half2_rn(v.x, v.y);
    __half2 h23 = __floats2half2_rn(v.z, v.w);
    float2 f01 = __half22float2(h01);
    float2 f23 = __half22float2(h23);
    __half2 l01 = __floats2half2_rn(v.x - f01.x, v.y - f01.y);
    __half2 l23 = __floats2half2_rn(v.z - f23.x, v.w - f23.y);
    hi.x = *(uint32_t*)&h01; hi.y = *(uint32_t*)&h23;
    lo.x = *(uint32_t*)&l01; lo.y = *(uint32_t*)&l23;
}

// Dynamic smem layout (halves):
//   WsHi [128][136]  at 0        (17408)
//   WsLo [128][136]  at 17408
//   AsHi [2][128][40] at 34816   (2*5120)
//   AsLo [2][128][40] at 45056
#define SM_WHI 0
#define SM_WLO 17408
#define SM_AHI 34816
#define SM_ALO 45056
#define SM_TOTAL_HALVES 55296   // 110592 bytes

// O[M,128] = A[M,128] @ W[128,128]; hi/lo fp16 split, 3 MMAs per k16 step.
// W resident in smem (staged once); A 32-k chunks double-buffered with
// register prefetch -> one __syncthreads per chunk, LDG hidden behind MMAs.
__global__ __launch_bounds__(256, 2) void k_gemm_tc(const float* __restrict__ Aext,
                                                    const float* __restrict__ W,
                                                    int src_sel /*0=Aext 1=g_h1*/) {
    extern __shared__ __half sh[];
    const float* A = src_sel ? g_h1 : Aext;
    __half* O = g_hw;

    int tid = threadIdx.x;
    int wid = tid >> 5, lane = tid & 31;
    int mrow = (wid >> 1) * 32;          // warp row offset in tile
    int ncol0 = (wid & 1) * 64;          // warp col offset
    int row0 = blockIdx.x * 128;

    uint32_t sbase = (uint32_t)__cvta_generic_to_shared(sh);
    uint32_t sWhi = sbase + SM_WHI * 2, sWlo = sbase + SM_WLO * 2;
    uint32_t sAhi = sbase + SM_AHI * 2, sAlo = sbase + SM_ALO * 2;

    // ---- stage all of W (hi/lo) once: 4096 float4 / 256 thr = 16 each ----
#pragma unroll
    for (int j = 0; j < 16; j++) {
        int q = tid + j * 256;
        int br = q >> 5, bc = (q & 31) * 4;
        float4 v = *(const float4*)&W[br * CF + bc];
        uint2 hi, lo;
        cvt_hilo(v, hi, lo);
        *(uint2*)&sh[SM_WHI + br * 136 + bc] = hi;
        *(uint2*)&sh[SM_WLO + br * 136 + bc] = lo;
    }
    // ---- stage A chunk 0 ----
    {
        int row = tid >> 3, cg = tid & 7;
#pragma unroll
        for (int j = 0; j < 4; j++) {
            int r = row + j * 32;
            int gr = row0 + r;
            float4 v = make_float4(0.f, 0.f, 0.f, 0.f);
            if (gr < NN) v = *(const float4*)&A[gr * CF + cg * 4];
            uint2 hi, lo;
            cvt_hilo(v, hi, lo);
            *(uint2*)&sh[SM_AHI + r * 40 + cg * 4] = hi;
            *(uint2*)&sh[SM_ALO + r * 40 + cg * 4] = lo;
        }
    }
    __syncthreads();

    float acc[2][8][4];
#pragma unroll
    for (int mb = 0; mb < 2; mb++)
#pragma unroll
        for (int nt = 0; nt < 8; nt++)
#pragma unroll
            for (int i = 0; i < 4; i++) acc[mb][nt][i] = 0.f;

    int prow = tid >> 3, pcg = tid & 7;   // prefetch coords
#pragma unroll
    for (int kc = 0; kc < 4; kc++) {
        int buf = kc & 1, nbuf = buf ^ 1;
        // prefetch next A chunk into registers (issued before the MMAs)
        float4 pf[4];
        if (kc < 3) {
#pragma unroll
            for (int j = 0; j < 4; j++) {
                int gr = row0 + prow + j * 32;
                pf[j] = make_float4(0.f, 0.f, 0.f, 0.f);
                if (gr < NN)
                    pf[j] = *(const float4*)&A[gr * CF + (kc + 1) * 32 + pcg * 4];
            }
        }
        // compute on current buffer, W slice kc*32
#pragma unroll
        for (int ks = 0; ks < 2; ks++) {
            int kb = ks * 16;
            uint32_t ah[2][4], al[2][4];
            int arow = mrow + (lane & 15);
            int acol = kb + ((lane & 16) >> 1);
#pragma unroll
            for (int mb = 0; mb < 2; mb++) {
                uint32_t off = (uint32_t)((buf * 5120 + (arow + mb * 16) * 40 + acol) * 2);
                ldsm_x4(ah[mb][0], ah[mb][1], ah[mb][2], ah[mb][3], sAhi + off);
                ldsm_x4(al[mb][0], al[mb][1], al[mb][2], al[mb][3], sAlo + off);
            }
            int krow = kc * 32 + kb + (lane & 7) + (lane & 8);
            int ncol = ncol0 + ((lane & 16) >> 1);
#pragma unroll
            for (int p = 0; p < 4; p++) {
                uint32_t off = (uint32_t)((krow * 136 + ncol + p * 16) * 2);
                uint32_t bh0, bh1, bh2, bh3, bl0, bl1, bl2, bl3;
                ldsm_x4_t(bh0, bh1, bh2, bh3, sWhi + off);
                ldsm_x4_t(bl0, bl1, bl2, bl3, sWlo + off);
#pragma unroll
                for (int mb = 0; mb < 2; mb++) {
                    mma16(acc[mb][2 * p], ah[mb], bh0, bh1);
                    mma16(acc[mb][2 * p], al[mb], bh0, bh1);
                    mma16(acc[mb][2 * p], ah[mb], bl0, bl1);
                    mma16(acc[mb][2 * p + 1], ah[mb], bh2, bh3);
                    mma16(acc[mb][2 * p + 1], al[mb], bh2, bh3);
                    mma16(acc[mb][2 * p + 1], ah[mb], bl2, bl3);
                }
            }
        }
        // store prefetched chunk into the other buffer
        if (kc < 3) {
#pragma unroll
            for (int j = 0; j < 4; j++) {
                int r = prow + j * 32;
                uint2 hi, lo;
                cvt_hilo(pf[j], hi, lo);
                *(uint2*)&sh[SM_AHI + nbuf * 5120 + r * 40 + pcg * 4] = hi;
                *(uint2*)&sh[SM_ALO + nbuf * 5120 + r * 40 + pcg * 4] = lo;
            }
            __syncthreads();
        }
    }

    int g = lane >> 2, tg = lane & 3;
#pragma unroll
    for (int mb = 0; mb < 2; mb++) {
#pragma unroll
        for (int nt = 0; nt < 8; nt++) {
            int r = row0 + mrow + mb * 16 + g;
            int c = ncol0 + nt * 8 + tg * 2;
            if (r < NN)
                *(__half2*)&O[r * CF + c] =
                    __floats2half2_rn(acc[mb][nt][0], acc[mb][nt][1]);
            if (r + 8 < NN)
                *(__half2*)&O[(r + 8) * CF + c] =
                    __floats2half2_rn(acc[mb][nt][2], acc[mb][nt][3]);
        }
    }
}

// ---------------- aggregation ----------------------------------------------
__device__ __forceinline__ void acc8(float2& a0, float2& a1, float2& a2, float2& a3,
                                     uint4 u, float w) {
    float2 f0 = __half22float2(*reinterpret_cast<__half2*>(&u.x));
    float2 f1 = __half22float2(*reinterpret_cast<__half2*>(&u.y));
    float2 f2 = __half22float2(*reinterpret_cast<__half2*>(&u.z));
    float2 f3 = __half22float2(*reinterpret_cast<__half2*>(&u.w));
    a0.x = fmaf(f0.x, w, a0.x); a0.y = fmaf(f0.y, w, a0.y);
    a1.x = fmaf(f1.x, w, a1.x); a1.y = fmaf(f1.y, w, a1.y);
    a2.x = fmaf(f2.x, w, a2.x); a2.y = fmaf(f2.y, w, a2.y);
    a3.x = fmaf(f3.x, w, a3.x); a3.y = fmaf(f3.y, w, a3.y);
}

__global__ __launch_bounds__(256) void k_agg(const float* __restrict__ bias,
                                             int dst_sel /*1=g_h1(f32) 2=g_h2h(f16)*/,
                                             int do_relu) {
    int gw = (blockIdx.x * blockDim.x + threadIdx.x) >> 5;
    int lane = threadIdx.x & 31;
    if (gw >= NN) return;
    int half = lane >> 4, hl = lane & 15;
    const __half* hw = g_hw;

    float di = g_dinv[gw];
    float2 a0 = {0.f, 0.f}, a1 = {0.f, 0.f}, a2 = {0.f, 0.f}, a3 = {0.f, 0.f};

    if (half == 0) {   // self-loop term, counted once
        uint4 u = *(const uint4*)&hw[gw * CF + hl * 8];
        acc8(a0, a1, a2, a3, u, di * di);
    }

    int e = g_off[gw] + half, e1 = g_off[gw + 1];
    for (; e + 2 < e1; e += 4) {   // two edges per half-warp per iter
        int sA = g_csr_src[e], sB = g_csr_src[e + 2];
        float wA = g_dinv[sA] * di, wB = g_dinv[sB] * di;
        uint4 uA = *(const uint4*)&hw[sA * CF + hl * 8];
        uint4 uB = *(const uint4*)&hw[sB * CF + hl * 8];
        acc8(a0, a1, a2, a3, uA, wA);
        acc8(a0, a1, a2, a3, uB, wB);
    }
    if (e < e1) {
        int sA = g_csr_src[e];
        float wA = g_dinv[sA] * di;
        uint4 uA = *(const uint4*)&hw[sA * CF + hl * 8];
        acc8(a0, a1, a2, a3, uA, wA);
    }

    a0.x += __shfl_down_sync(0xffffffffu, a0.x, 16);
    a0.y += __shfl_down_sync(0xffffffffu, a0.y, 16);
    a1.x += __shfl_down_sync(0xffffffffu, a1.x, 16);
    a1.y += __shfl_down_sync(0xffffffffu, a1.y, 16);
    a2.x += __shfl_down_sync(0xffffffffu, a2.x, 16);
    a2.y += __shfl_down_sync(0xffffffffu, a2.y, 16);
    a3.x += __shfl_down_sync(0xffffffffu, a3.x, 16);
    a3.y += __shfl_down_sync(0xffffffffu, a3.y, 16);

    if (half == 0) {
        float4 b0 = *(const float4*)&bias[hl * 8];
        float4 b1 = *(const float4*)&bias[hl * 8 + 4];
        float r0 = a0.x + b0.x, r1 = a0.y + b0.y;
        float r2 = a1.x + b0.z, r3 = a1.y + b0.w;
        float r4 = a2.x + b1.x, r5 = a2.y + b1.y;
        float r6 = a3.x + b1.z, r7 = a3.y + b1.w;
        if (do_relu) {
            r0 = fmaxf(r0, 0.f); r1 = fmaxf(r1, 0.f);
            r2 = fmaxf(r2, 0.f); r3 = fmaxf(r3, 0.f);
            r4 = fmaxf(r4, 0.f); r5 = fmaxf(r5, 0.f);
            r6 = fmaxf(r6, 0.f); r7 = fmaxf(r7, 0.f);
        }
        if (dst_sel == 1) {
            *(float4*)&g_h1[gw * CF + hl * 8]     = make_float4(r0, r1, r2, r3);
            *(float4*)&g_h1[gw * CF + hl * 8 + 4] = make_float4(r4, r5, r6, r7);
        } else {
            __half2 p0 = __floats2half2_rn(r0, r1);
            __half2 p1 = __floats2half2_rn(r2, r3);
            __half2 p2 = __floats2half2_rn(r4, r5);
            __half2 p3 = __floats2half2_rn(r6, r7);
            uint4 u;
            u.x = *(uint32_t*)&p0; u.y = *(uint32_t*)&p1;
            u.z = *(uint32_t*)&p2; u.w = *(uint32_t*)&p3;
            *(uint4*)&g_h2h[gw * CF + hl * 8] = u;
        }
    }
}

// ---------------- subgraph mean-pool + classifier (fp16 h2) ----------------
__global__ __launch_bounds__(256) void k_pool(const void* __restrict__ sg,
                                              const float* __restrict__ Wc,
                                              const float* __restrict__ bc,
                                              float* __restrict__ out) {
    int gw = (blockIdx.x * blockDim.x + threadIdx.x) >> 5;
    int lane = threadIdx.x & 31;
    if (gw >= NS) return;
    int is64 = g_s64;
    int half = lane >> 4, hl = lane & 15;

    float a[8];
#pragma unroll
    for (int i = 0; i < 8; i++) a[i] = 0.f;
    int cnt = 0;
    for (int l = half; l < NL; l += 2) {
        int idx = load_idx(sg, gw * NL + l, is64);
        if (idx >= 0) {
            cnt++;
            uint4 u = *(const uint4*)&g_h2h[idx * CF + hl * 8];
            float2 f0 = __half22float2(*reinterpret_cast<__half2*>(&u.x));
            float2 f1 = __half22float2(*reinterpret_cast<__half2*>(&u.y));
            float2 f2 = __half22float2(*reinterpret_cast<__half2*>(&u.z));
            float2 f3 = __half22float2(*reinterpret_cast<__half2*>(&u.w));
            a[0] += f0.x; a[1] += f0.y; a[2] += f1.x; a[3] += f1.y;
            a[4] += f2.x; a[5] += f2.y; a[6] += f3.x; a[7] += f3.y;
        }
    }
#pragma unroll
    for (int i = 0; i < 8; i++)
        a[i] += __shfl_down_sync(0xffffffffu, a[i], 16);
    cnt += __shfl_down_sync(0xffffffffu, cnt, 16);

    float inv = 1.0f / (float)(cnt > 0 ? cnt : 1);
#pragma unroll
    for (int i = 0; i < 8; i++) a[i] *= inv;

    float res[NCLS];
#pragma unroll
    for (int c = 0; c < NCLS; c++) {
        float v = 0.f;
#pragma unroll
        for (int i = 0; i < 8; i++) v += a[i] * Wc[(hl * 8 + i) * NCLS + c];
        res[c] = v;
    }
#pragma unroll
    for (int c = 0; c < NCLS; c++) {
        float v = res[c];
#pragma unroll
        for (int o = 8; o > 0; o >>= 1) v += __shfl_xor_sync(0xffffffffu, v, o);
        if (lane == 0) out[gw * NCLS + c] = v + bc[c];
    }
}

// ---------------- launch ----------------------------------------------------
extern "C" void kernel_launch(void* const* d_in, const int* in_sizes, int n_in,
                              void* d_out, int out_size) {
    const float* x  = (const float*)d_in[0];   // (N,1,128) contiguous
    const void*  ei = d_in[1];                 // (2,E) int64 or int32
    const void*  sg = d_in[2];                 // (S,64) int64 or int32
    const float* W1 = (const float*)d_in[3];
    const float* b1 = (const float*)d_in[4];
    const float* W2 = (const float*)d_in[5];
    const float* b2 = (const float*)d_in[6];
    const float* Wc = (const float*)d_in[7];
    const float* bc = (const float*)d_in[8];
    float* out = (float*)d_out;

    const int TB = 256;
    const int nbE = (NE + TB - 1) / TB;
    const int nbG = (NN + 127) / 128;
    const int nbA = (NN * 32 + TB - 1) / TB;   // warp per node
    const int nbP = (NS * 32 + TB - 1) / TB;   // warp per subgraph
    const int GEMM_SMEM = SM_TOTAL_HALVES * 2; // 110592 bytes

    cudaFuncSetAttribute(k_gemm_tc, cudaFuncAttributeMaxDynamicSharedMemorySize,
                         GEMM_SMEM);           // host-side, idempotent, capture-safe

    // GEMM1 placed 4th: the profiler samples the 4th launch -> useful profile.
    k_detect<<<1, 32>>>((const unsigned int*)ei, (const unsigned int*)sg);
    k_count<<<nbE, TB>>>(ei);                  // g_cnt pre-zeroed (init / k_scan3)
    k_scan1<<<SCAN_NB, SCAN_BS>>>();
    k_gemm_tc<<<nbG, TB, GEMM_SMEM>>>(x, W1, 0);   // hw = x @ W1 (fp16 out)
    k_scan2<<<1, 256>>>();
    k_scan3<<<SCAN_NB, SCAN_BS>>>();
    k_fill<<<nbE, TB>>>(ei);

    k_agg<<<nbA, TB>>>(b1, 1, 1);              // h1 = relu(agg(hw) + b1)  (f32)
    k_gemm_tc<<<nbG, TB, GEMM_SMEM>>>(x, W2, 1);   // hw = h1 @ W2 (fp16 out)
    k_agg<<<nbA, TB>>>(b2, 2, 0);              // h2 = agg(hw) + b2        (f16)
    k_pool<<<nbP, TB>>>(sg, Wc, bc, out);
}

// round 6
// speedup vs baseline: 1.9948x; 1.0933x over previous
#include <cuda_runtime.h>
#include <cuda_fp16.h>
#include <cstdint>

#define NN   100000   // nodes
#define CF   128      // feature dim (C_in == H == 128)
#define NE   1600000  // edges
#define NS   4096     // subgraphs
#define NL   64       // max subgraph size
#define NCLS 10
#define SCAN_BS 512
#define SCAN_NB ((NN + SCAN_BS - 1) / SCAN_BS)

// ---------------- scratch (no allocations allowed -> __device__ globals) ---
__device__ int    g_cnt[NN];       // zeroed at load; re-zeroed per launch in k_scan3
__device__ float  g_dinv[NN];
__device__ int    g_off[NN + 1];
__device__ int    g_cur[NN];
__device__ int    g_bsum[SCAN_NB];
__device__ uint2  g_csr[NE];       // packed (src, bits(norm-weight))
__device__ __half g_hw[NN * CF];   // h @ W scratch (fp16)
__device__ float  g_h1[NN * CF];   // layer-1 output (fp32: feeds GEMM2)
__device__ __half g_h2h[NN * CF];  // layer-2 output (fp16: feeds pool only)
__device__ int    g_e64;           // edge_index is int64?
__device__ int    g_s64;           // subgraphs is int64?

// ---------------- dtype detection (int64 vs int32, decided on-device) ------
__global__ void k_detect(const unsigned int* __restrict__ ei,
                         const unsigned int* __restrict__ sg) {
    if (threadIdx.x == 0 && blockIdx.x == 0) {
        int e64 = 1;
        for (int i = 0; i < 64; i++)
            if (ei[2 * i + 1] != 0u) { e64 = 0; break; }
        int s64 = 1;
        for (int i = 0; i < 64; i++) {
            unsigned hi = sg[2 * i + 1];
            if (hi != 0u && hi != 0xFFFFFFFFu) { s64 = 0; break; }
        }
        g_e64 = e64;
        g_s64 = s64;
    }
}

__device__ __forceinline__ int load_idx(const void* p, int i, int is64) {
    return is64 ? (int)((const long long*)p)[i] : ((const int*)p)[i];
}

// ---------------- degree count ---------------------------------------------
__global__ void k_count(const void* __restrict__ ei) {
    int e = blockIdx.x * blockDim.x + threadIdx.x;
    if (e >= NE) return;
    int d = load_idx(ei, NE + e, g_e64);   // dst = second row
    atomicAdd(&g_cnt[d], 1);
}

// ---------------- scan1: per-block exclusive scan + dinv -------------------
__global__ void k_scan1() {
    __shared__ int sm[SCAN_BS];
    int gid = blockIdx.x * SCAN_BS + threadIdx.x;
    int v = (gid < NN) ? g_cnt[gid] : 0;
    if (gid < NN) g_dinv[gid] = rsqrtf((float)(v + 1));  // +1 self-loop
    sm[threadIdx.x] = v;
    __syncthreads();
    for (int ofs = 1; ofs < SCAN_BS; ofs <<= 1) {
        int t = (threadIdx.x >= ofs) ? sm[threadIdx.x - ofs] : 0;
        __syncthreads();
        sm[threadIdx.x] += t;
        __syncthreads();
    }
    if (gid < NN) g_off[gid] = sm[threadIdx.x] - v;          // exclusive
    if (threadIdx.x == SCAN_BS - 1) g_bsum[blockIdx.x] = sm[threadIdx.x];
}

// ---------------- scan2: parallel exclusive scan of block sums -------------
__global__ void k_scan2() {
    __shared__ int sm[256];
    int tid = threadIdx.x;
    int v = (tid < SCAN_NB) ? g_bsum[tid] : 0;
    sm[tid] = v;
    __syncthreads();
    for (int ofs = 1; ofs < 256; ofs <<= 1) {
        int t = (tid >= ofs) ? sm[tid - ofs] : 0;
        __syncthreads();
        sm[tid] += t;
        __syncthreads();
    }
    if (tid < SCAN_NB) g_bsum[tid] = sm[tid] - v;            // exclusive
}

// ---------------- scan3: finalize offsets, re-zero counts ------------------
__global__ void k_scan3() {
    int gid = blockIdx.x * SCAN_BS + threadIdx.x;
    if (gid < NN) {
        int o = g_off[gid] + g_bsum[blockIdx.x];
        g_off[gid] = o;
        g_cur[gid] = o;
        g_cnt[gid] = 0;                 // ready for the next graph replay
    }
    if (gid == 0) g_off[NN] = NE;
}

// ---------------- CSR fill: packed (src, weight) ---------------------------
__global__ void k_fill(const void* __restrict__ ei) {
    int e = blockIdx.x * blockDim.x + threadIdx.x;
    if (e >= NE) return;
    int is64 = g_e64;
    int s = load_idx(ei, e, is64);
    int d = load_idx(ei, NE + e, is64);
    int pos = atomicAdd(&g_cur[d], 1);
    float w = g_dinv[s] * g_dinv[d];
    g_csr[pos] = make_uint2((unsigned)s, __float_as_uint(w));
}

// ---------------- split-fp16 tensor-core GEMM ------------------------------
__device__ __forceinline__ void ldsm_x4(uint32_t& r0, uint32_t& r1,
                                        uint32_t& r2, uint32_t& r3, uint32_t a) {
    asm volatile("ldmatrix.sync.aligned.m8n8.x4.shared.b16 {%0,%1,%2,%3}, [%4];"
                 : "=r"(r0), "=r"(r1), "=r"(r2), "=r"(r3) : "r"(a));
}
__device__ __forceinline__ void ldsm_x4_t(uint32_t& r0, uint32_t& r1,
                                          uint32_t& r2, uint32_t& r3, uint32_t a) {
    asm volatile("ldmatrix.sync.aligned.m8n8.x4.trans.shared.b16 {%0,%1,%2,%3}, [%4];"
                 : "=r"(r0), "=r"(r1), "=r"(r2), "=r"(r3) : "r"(a));
}
__device__ __forceinline__ void mma16(float* d, const uint32_t* a,
                                      uint32_t b0, uint32_t b1) {
    asm volatile(
        "mma.sync.aligned.m16n8k16.row.col.f32.f16.f16.f32 "
        "{%0,%1,%2,%3}, {%4,%5,%6,%7}, {%8,%9}, {%0,%1,%2,%3};"
        : "+f"(d[0]), "+f"(d[1]), "+f"(d[2]), "+f"(d[3])
        : "r"(a[0]), "r"(a[1]), "r"(a[2]), "r"(a[3]), "r"(b0), "r"(b1));
}
__device__ __forceinline__ void cvt_hilo(float4 v, uint2& hi, uint2& lo) {
    __half2 h01 = __floats2half2_rn(v.x, v.y);
    __half2 h23 = __floats2half2_rn(v.z, v.w);
    float2 f01 = __half22float2(h01);
    float2 f23 = __half22float2(h23);
    __half2 l01 = __floats2half2_rn(v.x - f01.x, v.y - f01.y);
    __half2 l23 = __floats2half2_rn(v.z - f23.x, v.w - f23.y);
    hi.x = *(uint32_t*)&h01; hi.y = *(uint32_t*)&h23;
    lo.x = *(uint32_t*)&l01; lo.y = *(uint32_t*)&l23;
}
__device__ __forceinline__ uint2 cvt_hi(float4 v) {
    __half2 h01 = __floats2half2_rn(v.x, v.y);
    __half2 h23 = __floats2half2_rn(v.z, v.w);
    uint2 r;
    r.x = *(uint32_t*)&h01; r.y = *(uint32_t*)&h23;
    return r;
}

// Dynamic smem layout (halves):
//   WsHi [128][136]   at 0       (17408)
//   AsHi [2][128][40] at 17408   (10240)
//   AsLo [2][128][40] at 27648   (10240)
#define SM_WHI 0
#define SM_AHI 17408
#define SM_ALO 27648
#define SM_TOTAL_HALVES 37888   // 75776 bytes

// O[M,128] = A[M,128] @ W[128,128]; A hi/lo split fp16 (2 MMAs per step:
// AhBh + AlBh), W fp16-rounded (error absorbed by downstream averaging).
__global__ __launch_bounds__(256, 2) void k_gemm_tc(const float* __restrict__ Aext,
                                                    const float* __restrict__ W,
                                                    int src_sel /*0=Aext 1=g_h1*/) {
    extern __shared__ __half sh[];
    const float* A = src_sel ? g_h1 : Aext;
    __half* O = g_hw;

    int tid = threadIdx.x;
    int wid = tid >> 5, lane = tid & 31;
    int mrow = (wid >> 1) * 32;          // warp row offset in tile
    int ncol0 = (wid & 1) * 64;          // warp col offset
    int row0 = blockIdx.x * 128;

    uint32_t sbase = (uint32_t)__cvta_generic_to_shared(sh);
    uint32_t sWhi = sbase + SM_WHI * 2;
    uint32_t sAhi = sbase + SM_AHI * 2, sAlo = sbase + SM_ALO * 2;

    // ---- stage all of W (hi only) once ----
#pragma unroll
    for (int j = 0; j < 16; j++) {
        int q = tid + j * 256;
        int br = q >> 5, bc = (q & 31) * 4;
        float4 v = *(const float4*)&W[br * CF + bc];
        *(uint2*)&sh[SM_WHI + br * 136 + bc] = cvt_hi(v);
    }
    // ---- stage A chunk 0 ----
    {
        int row = tid >> 3, cg = tid & 7;
#pragma unroll
        for (int j = 0; j < 4; j++) {
            int r = row + j * 32;
            int gr = row0 + r;
            float4 v = make_float4(0.f, 0.f, 0.f, 0.f);
            if (gr < NN) v = *(const float4*)&A[gr * CF + cg * 4];
            uint2 hi, lo;
            cvt_hilo(v, hi, lo);
            *(uint2*)&sh[SM_AHI + r * 40 + cg * 4] = hi;
            *(uint2*)&sh[SM_ALO + r * 40 + cg * 4] = lo;
        }
    }
    __syncthreads();

    float acc[2][8][4];
#pragma unroll
    for (int mb = 0; mb < 2; mb++)
#pragma unroll
        for (int nt = 0; nt < 8; nt++)
#pragma unroll
            for (int i = 0; i < 4; i++) acc[mb][nt][i] = 0.f;

    int prow = tid >> 3, pcg = tid & 7;   // prefetch coords
#pragma unroll
    for (int kc = 0; kc < 4; kc++) {
        int buf = kc & 1, nbuf = buf ^ 1;
        float4 pf[4];
        if (kc < 3) {
#pragma unroll
            for (int j = 0; j < 4; j++) {
                int gr = row0 + prow + j * 32;
                pf[j] = make_float4(0.f, 0.f, 0.f, 0.f);
                if (gr < NN)
                    pf[j] = *(const float4*)&A[gr * CF + (kc + 1) * 32 + pcg * 4];
            }
        }
#pragma unroll
        for (int ks = 0; ks < 2; ks++) {
            int kb = ks * 16;
            uint32_t ah[2][4], al[2][4];
            int arow = mrow + (lane & 15);
            int acol = kb + ((lane & 16) >> 1);
#pragma unroll
            for (int mb = 0; mb < 2; mb++) {
                uint32_t off = (uint32_t)((buf * 5120 + (arow + mb * 16) * 40 + acol) * 2);
                ldsm_x4(ah[mb][0], ah[mb][1], ah[mb][2], ah[mb][3], sAhi + off);
                ldsm_x4(al[mb][0], al[mb][1], al[mb][2], al[mb][3], sAlo + off);
            }
            int krow = kc * 32 + kb + (lane & 7) + (lane & 8);
            int ncol = ncol0 + ((lane & 16) >> 1);
#pragma unroll
            for (int p = 0; p < 4; p++) {
                uint32_t off = (uint32_t)((krow * 136 + ncol + p * 16) * 2);
                uint32_t bh0, bh1, bh2, bh3;
                ldsm_x4_t(bh0, bh1, bh2, bh3, sWhi + off);
#pragma unroll
                for (int mb = 0; mb < 2; mb++) {
                    mma16(acc[mb][2 * p], ah[mb], bh0, bh1);
                    mma16(acc[mb][2 * p], al[mb], bh0, bh1);
                    mma16(acc[mb][2 * p + 1], ah[mb], bh2, bh3);
                    mma16(acc[mb][2 * p + 1], al[mb], bh2, bh3);
                }
            }
        }
        if (kc < 3) {
#pragma unroll
            for (int j = 0; j < 4; j++) {
                int r = prow + j * 32;
                uint2 hi, lo;
                cvt_hilo(pf[j], hi, lo);
                *(uint2*)&sh[SM_AHI + nbuf * 5120 + r * 40 + pcg * 4] = hi;
                *(uint2*)&sh[SM_ALO + nbuf * 5120 + r * 40 + pcg * 4] = lo;
            }
            __syncthreads();
        }
    }

    int g = lane >> 2, tg = lane & 3;
#pragma unroll
    for (int mb = 0; mb < 2; mb++) {
#pragma unroll
        for (int nt = 0; nt < 8; nt++) {
            int r = row0 + mrow + mb * 16 + g;
            int c = ncol0 + nt * 8 + tg * 2;
            if (r < NN)
                *(__half2*)&O[r * CF + c] =
                    __floats2half2_rn(acc[mb][nt][0], acc[mb][nt][1]);
            if (r + 8 < NN)
                *(__half2*)&O[(r + 8) * CF + c] =
                    __floats2half2_rn(acc[mb][nt][2], acc[mb][nt][3]);
        }
    }
}

// ---------------- aggregation ----------------------------------------------
__device__ __forceinline__ void acc8(float2& a0, float2& a1, float2& a2, float2& a3,
                                     uint4 u, float w) {
    float2 f0 = __half22float2(*reinterpret_cast<__half2*>(&u.x));
    float2 f1 = __half22float2(*reinterpret_cast<__half2*>(&u.y));
    float2 f2 = __half22float2(*reinterpret_cast<__half2*>(&u.z));
    float2 f3 = __half22float2(*reinterpret_cast<__half2*>(&u.w));
    a0.x = fmaf(f0.x, w, a0.x); a0.y = fmaf(f0.y, w, a0.y);
    a1.x = fmaf(f1.x, w, a1.x); a1.y = fmaf(f1.y, w, a1.y);
    a2.x = fmaf(f2.x, w, a2.x); a2.y = fmaf(f2.y, w, a2.y);
    a3.x = fmaf(f3.x, w, a3.x); a3.y = fmaf(f3.y, w, a3.y);
}

__global__ __launch_bounds__(256) void k_agg(const float* __restrict__ bias,
                                             int dst_sel /*1=g_h1(f32) 2=g_h2h(f16)*/,
                                             int do_relu) {
    int gw = (blockIdx.x * blockDim.x + threadIdx.x) >> 5;
    int lane = threadIdx.x & 31;
    if (gw >= NN) return;
    int half = lane >> 4, hl = lane & 15;
    const __half* hw = g_hw;

    float di = g_dinv[gw];
    float2 a0 = {0.f, 0.f}, a1 = {0.f, 0.f}, a2 = {0.f, 0.f}, a3 = {0.f, 0.f};

    if (half == 0) {   // self-loop term, counted once
        uint4 u = *(const uint4*)&hw[gw * CF + hl * 8];
        acc8(a0, a1, a2, a3, u, di * di);
    }

    int e = g_off[gw] + half, e1 = g_off[gw + 1];
    for (; e + 6 < e1; e += 8) {   // four edges per half-warp per iter
        uint2 sA = g_csr[e],     sB = g_csr[e + 2];
        uint2 sC = g_csr[e + 4], sD = g_csr[e + 6];
        uint4 uA = *(const uint4*)&hw[sA.x * CF + hl * 8];
        uint4 uB = *(const uint4*)&hw[sB.x * CF + hl * 8];
        uint4 uC = *(const uint4*)&hw[sC.x * CF + hl * 8];
        uint4 uD = *(const uint4*)&hw[sD.x * CF + hl * 8];
        acc8(a0, a1, a2, a3, uA, __uint_as_float(sA.y));
        acc8(a0, a1, a2, a3, uB, __uint_as_float(sB.y));
        acc8(a0, a1, a2, a3, uC, __uint_as_float(sC.y));
        acc8(a0, a1, a2, a3, uD, __uint_as_float(sD.y));
    }
    for (; e < e1; e += 2) {
        uint2 sA = g_csr[e];
        uint4 uA = *(const uint4*)&hw[sA.x * CF + hl * 8];
        acc8(a0, a1, a2, a3, uA, __uint_as_float(sA.y));
    }

    a0.x += __shfl_down_sync(0xffffffffu, a0.x, 16);
    a0.y += __shfl_down_sync(0xffffffffu, a0.y, 16);
    a1.x += __shfl_down_sync(0xffffffffu, a1.x, 16);
    a1.y += __shfl_down_sync(0xffffffffu, a1.y, 16);
    a2.x += __shfl_down_sync(0xffffffffu, a2.x, 16);
    a2.y += __shfl_down_sync(0xffffffffu, a2.y, 16);
    a3.x += __shfl_down_sync(0xffffffffu, a3.x, 16);
    a3.y += __shfl_down_sync(0xffffffffu, a3.y, 16);

    if (half == 0) {
        float4 b0 = *(const float4*)&bias[hl * 8];
        float4 b1 = *(const float4*)&bias[hl * 8 + 4];
        float r0 = a0.x + b0.x, r1 = a0.y + b0.y;
        float r2 = a1.x + b0.z, r3 = a1.y + b0.w;
        float r4 = a2.x + b1.x, r5 = a2.y + b1.y;
        float r6 = a3.x + b1.z, r7 = a3.y + b1.w;
        if (do_relu) {
            r0 = fmaxf(r0, 0.f); r1 = fmaxf(r1, 0.f);
            r2 = fmaxf(r2, 0.f); r3 = fmaxf(r3, 0.f);
            r4 = fmaxf(r4, 0.f); r5 = fmaxf(r5, 0.f);
            r6 = fmaxf(r6, 0.f); r7 = fmaxf(r7, 0.f);
        }
        if (dst_sel == 1) {
            *(float4*)&g_h1[gw * CF + hl * 8]     = make_float4(r0, r1, r2, r3);
            *(float4*)&g_h1[gw * CF + hl * 8 + 4] = make_float4(r4, r5, r6, r7);
        } else {
            __half2 p0 = __floats2half2_rn(r0, r1);
            __half2 p1 = __floats2half2_rn(r2, r3);
            __half2 p2 = __floats2half2_rn(r4, r5);
            __half2 p3 = __floats2half2_rn(r6, r7);
            uint4 u;
            u.x = *(uint32_t*)&p0; u.y = *(uint32_t*)&p1;
            u.z = *(uint32_t*)&p2; u.w = *(uint32_t*)&p3;
            *(uint4*)&g_h2h[gw * CF + hl * 8] = u;
        }
    }
}

// ---------------- subgraph mean-pool + classifier (fp16 h2) ----------------
__global__ __launch_bounds__(256) void k_pool(const void* __restrict__ sg,
                                              const float* __restrict__ Wc,
                                              const float* __restrict__ bc,
                                              float* __restrict__ out) {
    int gw = (blockIdx.x * blockDim.x + threadIdx.x) >> 5;
    int lane = threadIdx.x & 31;
    if (gw >= NS) return;
    int is64 = g_s64;
    int half = lane >> 4, hl = lane & 15;

    float a[8];
#pragma unroll
    for (int i = 0; i < 8; i++) a[i] = 0.f;
    int cnt = 0;
    for (int l = half; l < NL; l += 2) {
        int idx = load_idx(sg, gw * NL + l, is64);
        if (idx >= 0) {
            cnt++;
            uint4 u = *(const uint4*)&g_h2h[idx * CF + hl * 8];
            float2 f0 = __half22float2(*reinterpret_cast<__half2*>(&u.x));
            float2 f1 = __half22float2(*reinterpret_cast<__half2*>(&u.y));
            float2 f2 = __half22float2(*reinterpret_cast<__half2*>(&u.z));
            float2 f3 = __half22float2(*reinterpret_cast<__half2*>(&u.w));
            a[0] += f0.x; a[1] += f0.y; a[2] += f1.x; a[3] += f1.y;
            a[4] += f2.x; a[5] += f2.y; a[6] += f3.x; a[7] += f3.y;
        }
    }
#pragma unroll
    for (int i = 0; i < 8; i++)
        a[i] += __shfl_down_sync(0xffffffffu, a[i], 16);
    cnt += __shfl_down_sync(0xffffffffu, cnt, 16);

    float inv = 1.0f / (float)(cnt > 0 ? cnt : 1);
#pragma unroll
    for (int i = 0; i < 8; i++) a[i] *= inv;

    float res[NCLS];
#pragma unroll
    for (int c = 0; c < NCLS; c++) {
        float v = 0.f;
#pragma unroll
        for (int i = 0; i < 8; i++) v += a[i] * Wc[(hl * 8 + i) * NCLS + c];
        res[c] = v;
    }
#pragma unroll
    for (int c = 0; c < NCLS; c++) {
        float v = res[c];
#pragma unroll
        for (int o = 8; o > 0; o >>= 1) v += __shfl_xor_sync(0xffffffffu, v, o);
        if (lane == 0) out[gw * NCLS + c] = v + bc[c];
    }
}

// ---------------- launch ----------------------------------------------------
extern "C" void kernel_launch(void* const* d_in, const int* in_sizes, int n_in,
                              void* d_out, int out_size) {
    const float* x  = (const float*)d_in[0];   // (N,1,128) contiguous
    const void*  ei = d_in[1];                 // (2,E) int64 or int32
    const void*  sg = d_in[2];                 // (S,64) int64 or int32
    const float* W1 = (const float*)d_in[3];
    const float* b1 = (const float*)d_in[4];
    const float* W2 = (const float*)d_in[5];
    const float* b2 = (const float*)d_in[6];
    const float* Wc = (const float*)d_in[7];
    const float* bc = (const float*)d_in[8];
    float* out = (float*)d_out;

    const int TB = 256;
    const int nbE = (NE + TB - 1) / TB;
    const int nbG = (NN + 127) / 128;
    const int nbA = (NN * 32 + TB - 1) / TB;   // warp per node
    const int nbP = (NS * 32 + TB - 1) / TB;   // warp per subgraph
    const int GEMM_SMEM = SM_TOTAL_HALVES * 2; // 75776 bytes

    cudaFuncSetAttribute(k_gemm_tc, cudaFuncAttributeMaxDynamicSharedMemorySize,
                         GEMM_SMEM);           // host-side, idempotent, capture-safe

    // GEMM1 placed 4th: the profiler samples the 4th launch -> useful profile.
    k_detect<<<1, 32>>>((const unsigned int*)ei, (const unsigned int*)sg);
    k_count<<<nbE, TB>>>(ei);                  // g_cnt pre-zeroed (init / k_scan3)
    k_scan1<<<SCAN_NB, SCAN_BS>>>();
    k_gemm_tc<<<nbG, TB, GEMM_SMEM>>>(x, W1, 0);   // hw = x @ W1 (fp16 out)
    k_scan2<<<1, 256>>>();
    k_scan3<<<SCAN_NB, SCAN_BS>>>();
    k_fill<<<nbE, TB>>>(ei);

    k_agg<<<nbA, TB>>>(b1, 1, 1);              // h1 = relu(agg(hw) + b1)  (f32)
    k_gemm_tc<<<nbG, TB, GEMM_SMEM>>>(x, W2, 1);   // hw = h1 @ W2 (fp16 out)
    k_agg<<<nbA, TB>>>(b2, 2, 0);              // h2 = agg(hw) + b2        (f16)
    k_pool<<<nbP, TB>>>(sg, Wc, bc, out);
}

// round 8
// speedup vs baseline: 2.0507x; 1.0280x over previous
#include <cuda_runtime.h>
#include <cuda_fp16.h>
#include <cstdint>

#define NN   100000   // nodes
#define CF   128      // feature dim (C_in == H == 128)
#define NE   1600000  // edges
#define NS   4096     // subgraphs
#define NL   64       // max subgraph size
#define NCLS 10
#define SCAN_BS 512
#define SCAN_NB ((NN + SCAN_BS - 1) / SCAN_BS)

// ---------------- scratch (no allocations allowed -> __device__ globals) ---
__device__ int    g_cnt[NN];       // zeroed at load; re-zeroed per launch in k_scan3
__device__ float  g_dinv[NN];
__device__ int    g_off[NN + 1];
__device__ int    g_cur[NN];
__device__ int    g_bsum[SCAN_NB];
__device__ uint2  g_csr[NE];       // packed (src, bits(norm-weight))
__device__ __half g_hw[NN * CF];   // h @ W scratch (fp16)
__device__ float  g_h1[NN * CF];   // layer-1 output (fp32: feeds GEMM2)
__device__ __half g_h2h[NN * CF];  // layer-2 output (fp16: feeds pool only)

// ---------------- dtype detection helpers (per-block, no global state) -----
__device__ __forceinline__ int detect_e64(const unsigned int* ei) {
    // int64 nonneg indices < 2^31 have zero high words.
    for (int i = 0; i < 64; i++)
        if (ei[2 * i + 1] != 0u) return 0;
    return 1;
}
__device__ __forceinline__ int detect_s64(const unsigned int* sg) {
    // subgraphs contain -1 padding: int64 high words are 0 or 0xFFFFFFFF.
    for (int i = 0; i < 64; i++) {
        unsigned hi = sg[2 * i + 1];
        if (hi != 0u && hi != 0xFFFFFFFFu) return 0;
    }
    return 1;
}
__device__ __forceinline__ int load_idx(const void* p, int i, int is64) {
    return is64 ? (int)((const long long*)p)[i] : ((const int*)p)[i];
}

// ---------------- degree count ---------------------------------------------
__global__ void k_count(const void* __restrict__ ei) {
    __shared__ int s_e64;
    if (threadIdx.x == 0) s_e64 = detect_e64((const unsigned int*)ei);
    __syncthreads();
    int e = blockIdx.x * blockDim.x + threadIdx.x;
    if (e >= NE) return;
    int d = load_idx(ei, NE + e, s_e64);   // dst = second row
    atomicAdd(&g_cnt[d], 1);
}

// ---------------- scan1: per-block exclusive scan + dinv -------------------
__global__ void k_scan1() {
    __shared__ int sm[SCAN_BS];
    int gid = blockIdx.x * SCAN_BS + threadIdx.x;
    int v = (gid < NN) ? g_cnt[gid] : 0;
    if (gid < NN) g_dinv[gid] = rsqrtf((float)(v + 1));  // +1 self-loop
    sm[threadIdx.x] = v;
    __syncthreads();
    for (int ofs = 1; ofs < SCAN_BS; ofs <<= 1) {
        int t = (threadIdx.x >= ofs) ? sm[threadIdx.x - ofs] : 0;
        __syncthreads();
        sm[threadIdx.x] += t;
        __syncthreads();
    }
    if (gid < NN) g_off[gid] = sm[threadIdx.x] - v;          // exclusive
    if (threadIdx.x == SCAN_BS - 1) g_bsum[blockIdx.x] = sm[threadIdx.x];
}

// ---------------- scan3: block-prefix + finalize (scan2 folded in) ---------
__global__ void k_scan3() {
    __shared__ int s_pre;
    if (threadIdx.x < 32) {
        int r = 0;
        for (int b = threadIdx.x; b < (int)blockIdx.x; b += 32) r += g_bsum[b];
#pragma unroll
        for (int o = 16; o > 0; o >>= 1) r += __shfl_xor_sync(0xffffffffu, r, o);
        if (threadIdx.x == 0) s_pre = r;
    }
    __syncthreads();
    int gid = blockIdx.x * SCAN_BS + threadIdx.x;
    if (gid < NN) {
        int o = g_off[gid] + s_pre;
        g_off[gid] = o;
        g_cur[gid] = o;
        g_cnt[gid] = 0;                 // ready for the next graph replay
    }
    if (gid == 0) g_off[NN] = NE;
}

// ---------------- CSR fill: packed (src, weight) ---------------------------
__global__ void k_fill(const void* __restrict__ ei) {
    __shared__ int s_e64;
    if (threadIdx.x == 0) s_e64 = detect_e64((const unsigned int*)ei);
    __syncthreads();
    int e = blockIdx.x * blockDim.x + threadIdx.x;
    if (e >= NE) return;
    int s = load_idx(ei, e, s_e64);
    int d = load_idx(ei, NE + e, s_e64);
    int pos = atomicAdd(&g_cur[d], 1);
    float w = g_dinv[s] * g_dinv[d];
    g_csr[pos] = make_uint2((unsigned)s, __float_as_uint(w));
}

// ---------------- split-fp16 tensor-core GEMM ------------------------------
__device__ __forceinline__ void ldsm_x4(uint32_t& r0, uint32_t& r1,
                                        uint32_t& r2, uint32_t& r3, uint32_t a) {
    asm volatile("ldmatrix.sync.aligned.m8n8.x4.shared.b16 {%0,%1,%2,%3}, [%4];"
                 : "=r"(r0), "=r"(r1), "=r"(r2), "=r"(r3) : "r"(a));
}
__device__ __forceinline__ void ldsm_x4_t(uint32_t& r0, uint32_t& r1,
                                          uint32_t& r2, uint32_t& r3, uint32_t a) {
    asm volatile("ldmatrix.sync.aligned.m8n8.x4.trans.shared.b16 {%0,%1,%2,%3}, [%4];"
                 : "=r"(r0), "=r"(r1), "=r"(r2), "=r"(r3) : "r"(a));
}
__device__ __forceinline__ void mma16(float* d, const uint32_t* a,
                                      uint32_t b0, uint32_t b1) {
    asm volatile(
        "mma.sync.aligned.m16n8k16.row.col.f32.f16.f16.f32 "
        "{%0,%1,%2,%3}, {%4,%5,%6,%7}, {%8,%9}, {%0,%1,%2,%3};"
        : "+f"(d[0]), "+f"(d[1]), "+f"(d[2]), "+f"(d[3])
        : "r"(a[0]), "r"(a[1]), "r"(a[2]), "r"(a[3]), "r"(b0), "r"(b1));
}
__device__ __forceinline__ void cvt_hilo(float4 v, uint2& hi, uint2& lo) {
    __half2 h01 = __floats2half2_rn(v.x, v.y);
    __half2 h23 = __floats2half2_rn(v.z, v.w);
    float2 f01 = __half22float2(h01);
    float2 f23 = __half22float2(h23);
    __half2 l01 = __floats2half2_rn(v.x - f01.x, v.y - f01.y);
    __half2 l23 = __floats2half2_rn(v.z - f23.x, v.w - f23.y);
    hi.x = *(uint32_t*)&h01; hi.y = *(uint32_t*)&h23;
    lo.x = *(uint32_t*)&l01; lo.y = *(uint32_t*)&l23;
}
__device__ __forceinline__ uint2 cvt_hi(float4 v) {
    __half2 h01 = __floats2half2_rn(v.x, v.y);
    __half2 h23 = __floats2half2_rn(v.z, v.w);
    uint2 r;
    r.x = *(uint32_t*)&h01; r.y = *(uint32_t*)&h23;
    return r;
}

// Dynamic smem layout (halves):
//   WsHi [128][136]   at 0       (17408)
//   AsHi [2][128][40] at 17408   (10240)
//   AsLo [2][128][40] at 27648   (10240)
#define SM_WHI 0
#define SM_AHI 17408
#define SM_ALO 27648
#define SM_TOTAL_HALVES 37888   // 75776 bytes

// O[M,128] = A[M,128] @ W[128,128]; A hi/lo split fp16 (2 MMAs per step:
// AhBh + AlBh), W fp16-rounded (error absorbed by downstream averaging).
__global__ __launch_bounds__(256, 2) void k_gemm_tc(const float* __restrict__ Aext,
                                                    const float* __restrict__ W,
                                                    int src_sel /*0=Aext 1=g_h1*/) {
    extern __shared__ __half sh[];
    const float* A = src_sel ? g_h1 : Aext;
    __half* O = g_hw;

    int tid = threadIdx.x;
    int wid = tid >> 5, lane = tid & 31;
    int mrow = (wid >> 1) * 32;          // warp row offset in tile
    int ncol0 = (wid & 1) * 64;          // warp col offset
    int row0 = blockIdx.x * 128;

    uint32_t sbase = (uint32_t)__cvta_generic_to_shared(sh);
    uint32_t sWhi = sbase + SM_WHI * 2;
    uint32_t sAhi = sbase + SM_AHI * 2, sAlo = sbase + SM_ALO * 2;

    // ---- stage all of W (hi only) once ----
#pragma unroll
    for (int j = 0; j < 16; j++) {
        int q = tid + j * 256;
        int br = q >> 5, bc = (q & 31) * 4;
        float4 v = *(const float4*)&W[br * CF + bc];
        *(uint2*)&sh[SM_WHI + br * 136 + bc] = cvt_hi(v);
    }
    // ---- stage A chunk 0 ----
    {
        int row = tid >> 3, cg = tid & 7;
#pragma unroll
        for (int j = 0; j < 4; j++) {
            int r = row + j * 32;
            int gr = row0 + r;
            float4 v = make_float4(0.f, 0.f, 0.f, 0.f);
            if (gr < NN) v = *(const float4*)&A[gr * CF + cg * 4];
            uint2 hi, lo;
            cvt_hilo(v, hi, lo);
            *(uint2*)&sh[SM_AHI + r * 40 + cg * 4] = hi;
            *(uint2*)&sh[SM_ALO + r * 40 + cg * 4] = lo;
        }
    }
    __syncthreads();

    float acc[2][8][4];
#pragma unroll
    for (int mb = 0; mb < 2; mb++)
#pragma unroll
        for (int nt = 0; nt < 8; nt++)
#pragma unroll
            for (int i = 0; i < 4; i++) acc[mb][nt][i] = 0.f;

    int prow = tid >> 3, pcg = tid & 7;   // prefetch coords
#pragma unroll
    for (int kc = 0; kc < 4; kc++) {
        int buf = kc & 1, nbuf = buf ^ 1;
        float4 pf[4];
        if (kc < 3) {
#pragma unroll
            for (int j = 0; j < 4; j++) {
                int gr = row0 + prow + j * 32;
                pf[j] = make_float4(0.f, 0.f, 0.f, 0.f);
                if (gr < NN)
                    pf[j] = *(const float4*)&A[gr * CF + (kc + 1) * 32 + pcg * 4];
            }
        }
#pragma unroll
        for (int ks = 0; ks < 2; ks++) {
            int kb = ks * 16;
            uint32_t ah[2][4], al[2][4];
            int arow = mrow + (lane & 15);
            int acol = kb + ((lane & 16) >> 1);
#pragma unroll
            for (int mb = 0; mb < 2; mb++) {
                uint32_t off = (uint32_t)((buf * 5120 + (arow + mb * 16) * 40 + acol) * 2);
                ldsm_x4(ah[mb][0], ah[mb][1], ah[mb][2], ah[mb][3], sAhi + off);
                ldsm_x4(al[mb][0], al[mb][1], al[mb][2], al[mb][3], sAlo + off);
            }
            int krow = kc * 32 + kb + (lane & 7) + (lane & 8);
            int ncol = ncol0 + ((lane & 16) >> 1);
#pragma unroll
            for (int p = 0; p < 4; p++) {
                uint32_t off = (uint32_t)((krow * 136 + ncol + p * 16) * 2);
                uint32_t bh0, bh1, bh2, bh3;
                ldsm_x4_t(bh0, bh1, bh2, bh3, sWhi + off);
#pragma unroll
                for (int mb = 0; mb < 2; mb++) {
                    mma16(acc[mb][2 * p], ah[mb], bh0, bh1);
                    mma16(acc[mb][2 * p], al[mb], bh0, bh1);
                    mma16(acc[mb][2 * p + 1], ah[mb], bh2, bh3);
                    mma16(acc[mb][2 * p + 1], al[mb], bh2, bh3);
                }
            }
        }
        if (kc < 3) {
#pragma unroll
            for (int j = 0; j < 4; j++) {
                int r = prow + j * 32;
                uint2 hi, lo;
                cvt_hilo(pf[j], hi, lo);
                *(uint2*)&sh[SM_AHI + nbuf * 5120 + r * 40 + pcg * 4] = hi;
                *(uint2*)&sh[SM_ALO + nbuf * 5120 + r * 40 + pcg * 4] = lo;
            }
            __syncthreads();
        }
    }

    int g = lane >> 2, tg = lane & 3;
#pragma unroll
    for (int mb = 0; mb < 2; mb++) {
#pragma unroll
        for (int nt = 0; nt < 8; nt++) {
            int r = row0 + mrow + mb * 16 + g;
            int c = ncol0 + nt * 8 + tg * 2;
            if (r < NN)
                *(__half2*)&O[r * CF + c] =
                    __floats2half2_rn(acc[mb][nt][0], acc[mb][nt][1]);
            if (r + 8 < NN)
                *(__half2*)&O[(r + 8) * CF + c] =
                    __floats2half2_rn(acc[mb][nt][2], acc[mb][nt][3]);
        }
    }
}

// ---------------- aggregation ----------------------------------------------
__device__ __forceinline__ void acc8(float2& a0, float2& a1, float2& a2, float2& a3,
                                     uint4 u, float w) {
    float2 f0 = __half22float2(*reinterpret_cast<__half2*>(&u.x));
    float2 f1 = __half22float2(*reinterpret_cast<__half2*>(&u.y));
    float2 f2 = __half22float2(*reinterpret_cast<__half2*>(&u.z));
    float2 f3 = __half22float2(*reinterpret_cast<__half2*>(&u.w));
    a0.x = fmaf(f0.x, w, a0.x); a0.y = fmaf(f0.y, w, a0.y);
    a1.x = fmaf(f1.x, w, a1.x); a1.y = fmaf(f1.y, w, a1.y);
    a2.x = fmaf(f2.x, w, a2.x); a2.y = fmaf(f2.y, w, a2.y);
    a3.x = fmaf(f3.x, w, a3.x); a3.y = fmaf(f3.y, w, a3.y);
}

__global__ __launch_bounds__(256) void k_agg(const float* __restrict__ bias,
                                             int dst_sel /*1=g_h1(f32) 2=g_h2h(f16)*/,
                                             int do_relu) {
    int gw = (blockIdx.x * blockDim.x + threadIdx.x) >> 5;
    int lane = threadIdx.x & 31;
    if (gw >= NN) return;
    int half = lane >> 4, hl = lane & 15;
    const __half* hw = g_hw;

    float di = g_dinv[gw];
    float2 a0 = {0.f, 0.f}, a1 = {0.f, 0.f}, a2 = {0.f, 0.f}, a3 = {0.f, 0.f};

    if (half == 0) {   // self-loop term, counted once
        uint4 u = *(const uint4*)&hw[gw * CF + hl * 8];
        acc8(a0, a1, a2, a3, u, di * di);
    }

    int e = g_off[gw] + half, e1 = g_off[gw + 1];
    for (; e + 6 < e1; e += 8) {   // four edges per half-warp per iter
        uint2 sA = g_csr[e],     sB = g_csr[e + 2];
        uint2 sC = g_csr[e + 4], sD = g_csr[e + 6];
        uint4 uA = *(const uint4*)&hw[sA.x * CF + hl * 8];
        uint4 uB = *(const uint4*)&hw[sB.x * CF + hl * 8];
        uint4 uC = *(const uint4*)&hw[sC.x * CF + hl * 8];
        uint4 uD = *(const uint4*)&hw[sD.x * CF + hl * 8];
        acc8(a0, a1, a2, a3, uA, __uint_as_float(sA.y));
        acc8(a0, a1, a2, a3, uB, __uint_as_float(sB.y));
        acc8(a0, a1, a2, a3, uC, __uint_as_float(sC.y));
        acc8(a0, a1, a2, a3, uD, __uint_as_float(sD.y));
    }
    for (; e < e1; e += 2) {
        uint2 sA = g_csr[e];
        uint4 uA = *(const uint4*)&hw[sA.x * CF + hl * 8];
        acc8(a0, a1, a2, a3, uA, __uint_as_float(sA.y));
    }

    a0.x += __shfl_down_sync(0xffffffffu, a0.x, 16);
    a0.y += __shfl_down_sync(0xffffffffu, a0.y, 16);
    a1.x += __shfl_down_sync(0xffffffffu, a1.x, 16);
    a1.y += __shfl_down_sync(0xffffffffu, a1.y, 16);
    a2.x += __shfl_down_sync(0xffffffffu, a2.x, 16);
    a2.y += __shfl_down_sync(0xffffffffu, a2.y, 16);
    a3.x += __shfl_down_sync(0xffffffffu, a3.x, 16);
    a3.y += __shfl_down_sync(0xffffffffu, a3.y, 16);

    if (half == 0) {
        float4 b0 = *(const float4*)&bias[hl * 8];
        float4 b1 = *(const float4*)&bias[hl * 8 + 4];
        float r0 = a0.x + b0.x, r1 = a0.y + b0.y;
        float r2 = a1.x + b0.z, r3 = a1.y + b0.w;
        float r4 = a2.x + b1.x, r5 = a2.y + b1.y;
        float r6 = a3.x + b1.z, r7 = a3.y + b1.w;
        if (do_relu) {
            r0 = fmaxf(r0, 0.f); r1 = fmaxf(r1, 0.f);
            r2 = fmaxf(r2, 0.f); r3 = fmaxf(r3, 0.f);
            r4 = fmaxf(r4, 0.f); r5 = fmaxf(r5, 0.f);
            r6 = fmaxf(r6, 0.f); r7 = fmaxf(r7, 0.f);
        }
        if (dst_sel == 1) {
            *(float4*)&g_h1[gw * CF + hl * 8]     = make_float4(r0, r1, r2, r3);
            *(float4*)&g_h1[gw * CF + hl * 8 + 4] = make_float4(r4, r5, r6, r7);
        } else {
            __half2 p0 = __floats2half2_rn(r0, r1);
            __half2 p1 = __floats2half2_rn(r2, r3);
            __half2 p2 = __floats2half2_rn(r4, r5);
            __half2 p3 = __floats2half2_rn(r6, r7);
            uint4 u;
            u.x = *(uint32_t*)&p0; u.y = *(uint32_t*)&p1;
            u.z = *(uint32_t*)&p2; u.w = *(uint32_t*)&p3;
            *(uint4*)&g_h2h[gw * CF + hl * 8] = u;
        }
    }
}

// ---------------- subgraph mean-pool + classifier (fp16 h2) ----------------
__global__ __launch_bounds__(256) void k_pool(const void* __restrict__ sg,
                                              const float* __restrict__ Wc,
                                              const float* __restrict__ bc,
                                              float* __restrict__ out) {
    __shared__ int s_s64;
    if (threadIdx.x == 0) s_s64 = detect_s64((const unsigned int*)sg);
    __syncthreads();
    int gw = (blockIdx.x * blockDim.x + threadIdx.x) >> 5;
    int lane = threadIdx.x & 31;
    if (gw >= NS) return;
    int is64 = s_s64;
    int half = lane >> 4, hl = lane & 15;

    float a[8];
#pragma unroll
    for (int i = 0; i < 8; i++) a[i] = 0.f;
    int cnt = 0;
    for (int l = half; l < NL; l += 2) {
        int idx = load_idx(sg, gw * NL + l, is64);
        if (idx >= 0) {
            cnt++;
            uint4 u = *(const uint4*)&g_h2h[idx * CF + hl * 8];
            float2 f0 = __half22float2(*reinterpret_cast<__half2*>(&u.x));
            float2 f1 = __half22float2(*reinterpret_cast<__half2*>(&u.y));
            float2 f2 = __half22float2(*reinterpret_cast<__half2*>(&u.z));
            float2 f3 = __half22float2(*reinterpret_cast<__half2*>(&u.w));
            a[0] += f0.x; a[1] += f0.y; a[2] += f1.x; a[3] += f1.y;
            a[4] += f2.x; a[5] += f2.y; a[6] += f3.x; a[7] += f3.y;
        }
    }
#pragma unroll
    for (int i = 0; i < 8; i++)
        a[i] += __shfl_down_sync(0xffffffffu, a[i], 16);
    cnt += __shfl_down_sync(0xffffffffu, cnt, 16);

    float inv = 1.0f / (float)(cnt > 0 ? cnt : 1);
#pragma unroll
    for (int i = 0; i < 8; i++) a[i] *= inv;

    float res[NCLS];
#pragma unroll
    for (int c = 0; c < NCLS; c++) {
        float v = 0.f;
#pragma unroll
        for (int i = 0; i < 8; i++) v += a[i] * Wc[(hl * 8 + i) * NCLS + c];
        res[c] = v;
    }
#pragma unroll
    for (int c = 0; c < NCLS; c++) {
        float v = res[c];
#pragma unroll
        for (int o = 8; o > 0; o >>= 1) v += __shfl_xor_sync(0xffffffffu, v, o);
        if (lane == 0) out[gw * NCLS + c] = v + bc[c];
    }
}

// ---------------- launch ----------------------------------------------------
extern "C" void kernel_launch(void* const* d_in, const int* in_sizes, int n_in,
                              void* d_out, int out_size) {
    const float* x  = (const float*)d_in[0];   // (N,1,128) contiguous
    const void*  ei = d_in[1];                 // (2,E) int64 or int32
    const void*  sg = d_in[2];                 // (S,64) int64 or int32
    const float* W1 = (const float*)d_in[3];
    const float* b1 = (const float*)d_in[4];
    const float* W2 = (const float*)d_in[5];
    const float* b2 = (const float*)d_in[6];
    const float* Wc = (const float*)d_in[7];
    const float* bc = (const float*)d_in[8];
    float* out = (float*)d_out;

    const int TB = 256;
    const int nbE = (NE + TB - 1) / TB;
    const int nbG = (NN + 127) / 128;
    const int nbA = (NN * 32 + TB - 1) / TB;   // warp per node
    const int nbP = (NS * 32 + TB - 1) / TB;   // warp per subgraph
    const int GEMM_SMEM = SM_TOTAL_HALVES * 2; // 75776 bytes

    cudaFuncSetAttribute(k_gemm_tc, cudaFuncAttributeMaxDynamicSharedMemorySize,
                         GEMM_SMEM);           // host-side, idempotent, capture-safe

    // Fork: GEMM1 depends only on inputs (x, W1) -> run it on a side stream
    // concurrently with the CSR-build chain; join before agg1. Stream/events
    // are created per call (<=3 calls total; no device-memory allocation).
    cudaStream_t s2;
    cudaEvent_t evF, evJ;
    cudaStreamCreateWithFlags(&s2, cudaStreamNonBlocking);
    cudaEventCreateWithFlags(&evF, cudaEventDisableTiming);
    cudaEventCreateWithFlags(&evJ, cudaEventDisableTiming);

    cudaEventRecord(evF, 0);
    cudaStreamWaitEvent(s2, evF, 0);

    // main-stream prep chain
    k_count<<<nbE, TB>>>(ei);                  // g_cnt pre-zeroed (init / k_scan3)
    k_scan1<<<SCAN_NB, SCAN_BS>>>();
    k_scan3<<<SCAN_NB, SCAN_BS>>>();
    k_fill<<<nbE, TB>>>(ei);

    // side-stream GEMM1 (overlaps the prep chain)
    k_gemm_tc<<<nbG, TB, GEMM_SMEM, s2>>>(x, W1, 0);   // hw = x @ W1 (fp16 out)
    cudaEventRecord(evJ, s2);
    cudaStreamWaitEvent(0, evJ, 0);            // join: agg1 needs hw + CSR

    k_agg<<<nbA, TB>>>(b1, 1, 1);              // h1 = relu(agg(hw) + b1)  (f32)
    k_gemm_tc<<<nbG, TB, GEMM_SMEM>>>(x, W2, 1);   // hw = h1 @ W2 (fp16 out)
    k_agg<<<nbA, TB>>>(b2, 2, 0);              // h2 = agg(hw) + b2        (f16)
    k_pool<<<nbP, TB>>>(sg, Wc, bc, out);
}

// round 9
// speedup vs baseline: 2.1362x; 1.0417x over previous
#include <cuda_runtime.h>
#include <cuda_fp16.h>
#include <cstdint>

#define NN   100000   // nodes
#define CF   128      // feature dim (C_in == H == 128)
#define NE   1600000  // edges
#define NS   4096     // subgraphs
#define NL   64       // max subgraph size
#define NCLS 10
#define SCAN_BS 512
#define SCAN_NB ((NN + SCAN_BS - 1) / SCAN_BS)

// ---------------- scratch (no allocations allowed -> __device__ globals) ---
__device__ int    g_cnt[NN];       // zeroed at load; re-zeroed per launch in k_scan3
__device__ float  g_dinv[NN];
__device__ int    g_off[NN + 1];
__device__ int    g_cur[NN];
__device__ int    g_bsum[SCAN_NB];
__device__ uint2  g_csr[NE];       // packed (src, bits(norm-weight))
__device__ __half g_hw[NN * CF];   // h @ W scratch (fp16)
__device__ float  g_h1[NN * CF];   // layer-1 output (fp32: feeds GEMM2)
__device__ __half g_h2h[NN * CF];  // layer-2 output (fp16: feeds pool only)

// ---------------- dtype detection helpers (per-block, no global state) -----
__device__ __forceinline__ int detect_e64(const unsigned int* ei) {
    for (int i = 0; i < 64; i++)
        if (ei[2 * i + 1] != 0u) return 0;
    return 1;
}
__device__ __forceinline__ int detect_s64(const unsigned int* sg) {
    for (int i = 0; i < 64; i++) {
        unsigned hi = sg[2 * i + 1];
        if (hi != 0u && hi != 0xFFFFFFFFu) return 0;
    }
    return 1;
}
__device__ __forceinline__ int load_idx(const void* p, int i, int is64) {
    return is64 ? (int)((const long long*)p)[i] : ((const int*)p)[i];
}

// ---------------- degree count ---------------------------------------------
__global__ void k_count(const void* __restrict__ ei) {
    __shared__ int s_e64;
    if (threadIdx.x == 0) s_e64 = detect_e64((const unsigned int*)ei);
    __syncthreads();
    int e = blockIdx.x * blockDim.x + threadIdx.x;
    if (e >= NE) return;
    int d = load_idx(ei, NE + e, s_e64);   // dst = second row
    atomicAdd(&g_cnt[d], 1);
}

// ---------------- scan1: per-block exclusive scan + dinv -------------------
__global__ void k_scan1() {
    __shared__ int sm[SCAN_BS];
    int gid = blockIdx.x * SCAN_BS + threadIdx.x;
    int v = (gid < NN) ? g_cnt[gid] : 0;
    if (gid < NN) g_dinv[gid] = rsqrtf((float)(v + 1));  // +1 self-loop
    sm[threadIdx.x] = v;
    __syncthreads();
    for (int ofs = 1; ofs < SCAN_BS; ofs <<= 1) {
        int t = (threadIdx.x >= ofs) ? sm[threadIdx.x - ofs] : 0;
        __syncthreads();
        sm[threadIdx.x] += t;
        __syncthreads();
    }
    if (gid < NN) g_off[gid] = sm[threadIdx.x] - v;          // exclusive
    if (threadIdx.x == SCAN_BS - 1) g_bsum[blockIdx.x] = sm[threadIdx.x];
}

// ---------------- scan3: block-prefix + finalize (scan2 folded in) ---------
__global__ void k_scan3() {
    __shared__ int s_pre;
    if (threadIdx.x < 32) {
        int r = 0;
        for (int b = threadIdx.x; b < (int)blockIdx.x; b += 32) r += g_bsum[b];
#pragma unroll
        for (int o = 16; o > 0; o >>= 1) r += __shfl_xor_sync(0xffffffffu, r, o);
        if (threadIdx.x == 0) s_pre = r;
    }
    __syncthreads();
    int gid = blockIdx.x * SCAN_BS + threadIdx.x;
    if (gid < NN) {
        int o = g_off[gid] + s_pre;
        g_off[gid] = o;
        g_cur[gid] = o;
        g_cnt[gid] = 0;                 // ready for the next graph replay
    }
    if (gid == 0) g_off[NN] = NE;
}

// ---------------- CSR fill: packed (src, weight) ---------------------------
__global__ void k_fill(const void* __restrict__ ei) {
    __shared__ int s_e64;
    if (threadIdx.x == 0) s_e64 = detect_e64((const unsigned int*)ei);
    __syncthreads();
    int e = blockIdx.x * blockDim.x + threadIdx.x;
    if (e >= NE) return;
    int s = load_idx(ei, e, s_e64);
    int d = load_idx(ei, NE + e, s_e64);
    int pos = atomicAdd(&g_cur[d], 1);
    float w = g_dinv[s] * g_dinv[d];
    g_csr[pos] = make_uint2((unsigned)s, __float_as_uint(w));
}

// ---------------- fp16 tensor-core GEMM ------------------------------------
__device__ __forceinline__ void ldsm_x4(uint32_t& r0, uint32_t& r1,
                                        uint32_t& r2, uint32_t& r3, uint32_t a) {
    asm volatile("ldmatrix.sync.aligned.m8n8.x4.shared.b16 {%0,%1,%2,%3}, [%4];"
                 : "=r"(r0), "=r"(r1), "=r"(r2), "=r"(r3) : "r"(a));
}
__device__ __forceinline__ void ldsm_x4_t(uint32_t& r0, uint32_t& r1,
                                          uint32_t& r2, uint32_t& r3, uint32_t a) {
    asm volatile("ldmatrix.sync.aligned.m8n8.x4.trans.shared.b16 {%0,%1,%2,%3}, [%4];"
                 : "=r"(r0), "=r"(r1), "=r"(r2), "=r"(r3) : "r"(a));
}
__device__ __forceinline__ void mma16(float* d, const uint32_t* a,
                                      uint32_t b0, uint32_t b1) {
    asm volatile(
        "mma.sync.aligned.m16n8k16.row.col.f32.f16.f16.f32 "
        "{%0,%1,%2,%3}, {%4,%5,%6,%7}, {%8,%9}, {%0,%1,%2,%3};"
        : "+f"(d[0]), "+f"(d[1]), "+f"(d[2]), "+f"(d[3])
        : "r"(a[0]), "r"(a[1]), "r"(a[2]), "r"(a[3]), "r"(b0), "r"(b1));
}
__device__ __forceinline__ uint2 cvt_hi(float4 v) {
    __half2 h01 = __floats2half2_rn(v.x, v.y);
    __half2 h23 = __floats2half2_rn(v.z, v.w);
    uint2 r;
    r.x = *(uint32_t*)&h01; r.y = *(uint32_t*)&h23;
    return r;
}

// Dynamic smem layout (halves):
//   Ws [128][136]    at 0       (17408)
//   As [2][128][40]  at 17408   (10240)
#define SM_WHI 0
#define SM_AHI 17408
#define SM_TOTAL_HALVES 27648   // 55296 bytes

// O[M,128] = A[M,128] @ W[128,128]; plain fp16 inputs, fp32 accumulate.
// (A/W fp16 rounding ~2^-11 rel; final rel_err ~5e-4, under the 1e-3 gate.)
__global__ __launch_bounds__(256, 2) void k_gemm_tc(const float* __restrict__ Aext,
                                                    const float* __restrict__ W,
                                                    int src_sel /*0=Aext 1=g_h1*/) {
    extern __shared__ __half sh[];
    const float* A = src_sel ? g_h1 : Aext;
    __half* O = g_hw;

    int tid = threadIdx.x;
    int wid = tid >> 5, lane = tid & 31;
    int mrow = (wid >> 1) * 32;          // warp row offset in tile
    int ncol0 = (wid & 1) * 64;          // warp col offset
    int row0 = blockIdx.x * 128;

    uint32_t sbase = (uint32_t)__cvta_generic_to_shared(sh);
    uint32_t sWhi = sbase + SM_WHI * 2;
    uint32_t sAhi = sbase + SM_AHI * 2;

    // ---- stage all of W once (fp16) ----
#pragma unroll
    for (int j = 0; j < 16; j++) {
        int q = tid + j * 256;
        int br = q >> 5, bc = (q & 31) * 4;
        float4 v = *(const float4*)&W[br * CF + bc];
        *(uint2*)&sh[SM_WHI + br * 136 + bc] = cvt_hi(v);
    }
    // ---- stage A chunk 0 ----
    {
        int row = tid >> 3, cg = tid & 7;
#pragma unroll
        for (int j = 0; j < 4; j++) {
            int r = row + j * 32;
            int gr = row0 + r;
            float4 v = make_float4(0.f, 0.f, 0.f, 0.f);
            if (gr < NN) v = *(const float4*)&A[gr * CF + cg * 4];
            *(uint2*)&sh[SM_AHI + r * 40 + cg * 4] = cvt_hi(v);
        }
    }
    __syncthreads();

    float acc[2][8][4];
#pragma unroll
    for (int mb = 0; mb < 2; mb++)
#pragma unroll
        for (int nt = 0; nt < 8; nt++)
#pragma unroll
            for (int i = 0; i < 4; i++) acc[mb][nt][i] = 0.f;

    int prow = tid >> 3, pcg = tid & 7;   // prefetch coords
#pragma unroll
    for (int kc = 0; kc < 4; kc++) {
        int buf = kc & 1, nbuf = buf ^ 1;
        float4 pf[4];
        if (kc < 3) {
#pragma unroll
            for (int j = 0; j < 4; j++) {
                int gr = row0 + prow + j * 32;
                pf[j] = make_float4(0.f, 0.f, 0.f, 0.f);
                if (gr < NN)
                    pf[j] = *(const float4*)&A[gr * CF + (kc + 1) * 32 + pcg * 4];
            }
        }
#pragma unroll
        for (int ks = 0; ks < 2; ks++) {
            int kb = ks * 16;
            uint32_t ah[2][4];
            int arow = mrow + (lane & 15);
            int acol = kb + ((lane & 16) >> 1);
#pragma unroll
            for (int mb = 0; mb < 2; mb++) {
                uint32_t off = (uint32_t)((buf * 5120 + (arow + mb * 16) * 40 + acol) * 2);
                ldsm_x4(ah[mb][0], ah[mb][1], ah[mb][2], ah[mb][3], sAhi + off);
            }
            int krow = kc * 32 + kb + (lane & 7) + (lane & 8);
            int ncol = ncol0 + ((lane & 16) >> 1);
#pragma unroll
            for (int p = 0; p < 4; p++) {
                uint32_t off = (uint32_t)((krow * 136 + ncol + p * 16) * 2);
                uint32_t bh0, bh1, bh2, bh3;
                ldsm_x4_t(bh0, bh1, bh2, bh3, sWhi + off);
#pragma unroll
                for (int mb = 0; mb < 2; mb++) {
                    mma16(acc[mb][2 * p], ah[mb], bh0, bh1);
                    mma16(acc[mb][2 * p + 1], ah[mb], bh2, bh3);
                }
            }
        }
        if (kc < 3) {
#pragma unroll
            for (int j = 0; j < 4; j++) {
                int r = prow + j * 32;
                *(uint2*)&sh[SM_AHI + nbuf * 5120 + r * 40 + pcg * 4] = cvt_hi(pf[j]);
            }
            __syncthreads();
        }
    }

    int g = lane >> 2, tg = lane & 3;
#pragma unroll
    for (int mb = 0; mb < 2; mb++) {
#pragma unroll
        for (int nt = 0; nt < 8; nt++) {
            int r = row0 + mrow + mb * 16 + g;
            int c = ncol0 + nt * 8 + tg * 2;
            if (r < NN)
                *(__half2*)&O[r * CF + c] =
                    __floats2half2_rn(acc[mb][nt][0], acc[mb][nt][1]);
            if (r + 8 < NN)
                *(__half2*)&O[(r + 8) * CF + c] =
                    __floats2half2_rn(acc[mb][nt][2], acc[mb][nt][3]);
        }
    }
}

// ---------------- aggregation ----------------------------------------------
__device__ __forceinline__ void acc8(float2& a0, float2& a1, float2& a2, float2& a3,
                                     uint4 u, float w) {
    float2 f0 = __half22float2(*reinterpret_cast<__half2*>(&u.x));
    float2 f1 = __half22float2(*reinterpret_cast<__half2*>(&u.y));
    float2 f2 = __half22float2(*reinterpret_cast<__half2*>(&u.z));
    float2 f3 = __half22float2(*reinterpret_cast<__half2*>(&u.w));
    a0.x = fmaf(f0.x, w, a0.x); a0.y = fmaf(f0.y, w, a0.y);
    a1.x = fmaf(f1.x, w, a1.x); a1.y = fmaf(f1.y, w, a1.y);
    a2.x = fmaf(f2.x, w, a2.x); a2.y = fmaf(f2.y, w, a2.y);
    a3.x = fmaf(f3.x, w, a3.x); a3.y = fmaf(f3.y, w, a3.y);
}

__global__ __launch_bounds__(256) void k_agg(const float* __restrict__ bias,
                                             int dst_sel /*1=g_h1(f32) 2=g_h2h(f16)*/,
                                             int do_relu) {
    int gw = (blockIdx.x * blockDim.x + threadIdx.x) >> 5;
    int lane = threadIdx.x & 31;
    if (gw >= NN) return;
    int half = lane >> 4, hl = lane & 15;
    const __half* hw = g_hw;

    float di = g_dinv[gw];
    float2 a0 = {0.f, 0.f}, a1 = {0.f, 0.f}, a2 = {0.f, 0.f}, a3 = {0.f, 0.f};

    if (half == 0) {   // self-loop term, counted once
        uint4 u = *(const uint4*)&hw[gw * CF + hl * 8];
        acc8(a0, a1, a2, a3, u, di * di);
    }

    int e = g_off[gw] + half, e1 = g_off[gw + 1];
    for (; e + 6 < e1; e += 8) {   // four edges per half-warp per iter
        uint2 sA = g_csr[e],     sB = g_csr[e + 2];
        uint2 sC = g_csr[e + 4], sD = g_csr[e + 6];
        uint4 uA = *(const uint4*)&hw[sA.x * CF + hl * 8];
        uint4 uB = *(const uint4*)&hw[sB.x * CF + hl * 8];
        uint4 uC = *(const uint4*)&hw[sC.x * CF + hl * 8];
        uint4 uD = *(const uint4*)&hw[sD.x * CF + hl * 8];
        acc8(a0, a1, a2, a3, uA, __uint_as_float(sA.y));
        acc8(a0, a1, a2, a3, uB, __uint_as_float(sB.y));
        acc8(a0, a1, a2, a3, uC, __uint_as_float(sC.y));
        acc8(a0, a1, a2, a3, uD, __uint_as_float(sD.y));
    }
    for (; e < e1; e += 2) {
        uint2 sA = g_csr[e];
        uint4 uA = *(const uint4*)&hw[sA.x * CF + hl * 8];
        acc8(a0, a1, a2, a3, uA, __uint_as_float(sA.y));
    }

    a0.x += __shfl_down_sync(0xffffffffu, a0.x, 16);
    a0.y += __shfl_down_sync(0xffffffffu, a0.y, 16);
    a1.x += __shfl_down_sync(0xffffffffu, a1.x, 16);
    a1.y += __shfl_down_sync(0xffffffffu, a1.y, 16);
    a2.x += __shfl_down_sync(0xffffffffu, a2.x, 16);
    a2.y += __shfl_down_sync(0xffffffffu, a2.y, 16);
    a3.x += __shfl_down_sync(0xffffffffu, a3.x, 16);
    a3.y += __shfl_down_sync(0xffffffffu, a3.y, 16);

    if (half == 0) {
        float4 b0 = *(const float4*)&bias[hl * 8];
        float4 b1 = *(const float4*)&bias[hl * 8 + 4];
        float r0 = a0.x + b0.x, r1 = a0.y + b0.y;
        float r2 = a1.x + b0.z, r3 = a1.y + b0.w;
        float r4 = a2.x + b1.x, r5 = a2.y + b1.y;
        float r6 = a3.x + b1.z, r7 = a3.y + b1.w;
        if (do_relu) {
            r0 = fmaxf(r0, 0.f); r1 = fmaxf(r1, 0.f);
            r2 = fmaxf(r2, 0.f); r3 = fmaxf(r3, 0.f);
            r4 = fmaxf(r4, 0.f); r5 = fmaxf(r5, 0.f);
            r6 = fmaxf(r6, 0.f); r7 = fmaxf(r7, 0.f);
        }
        if (dst_sel == 1) {
            *(float4*)&g_h1[gw * CF + hl * 8]     = make_float4(r0, r1, r2, r3);
            *(float4*)&g_h1[gw * CF + hl * 8 + 4] = make_float4(r4, r5, r6, r7);
        } else {
            __half2 p0 = __floats2half2_rn(r0, r1);
            __half2 p1 = __floats2half2_rn(r2, r3);
            __half2 p2 = __floats2half2_rn(r4, r5);
            __half2 p3 = __floats2half2_rn(r6, r7);
            uint4 u;
            u.x = *(uint32_t*)&p0; u.y = *(uint32_t*)&p1;
            u.z = *(uint32_t*)&p2; u.w = *(uint32_t*)&p3;
            *(uint4*)&g_h2h[gw * CF + hl * 8] = u;
        }
    }
}

// ---------------- subgraph mean-pool + classifier (fp16 h2) ----------------
__global__ __launch_bounds__(256) void k_pool(const void* __restrict__ sg,
                                              const float* __restrict__ Wc,
                                              const float* __restrict__ bc,
                                              float* __restrict__ out) {
    __shared__ int s_s64;
    if (threadIdx.x == 0) s_s64 = detect_s64((const unsigned int*)sg);
    __syncthreads();
    int gw = (blockIdx.x * blockDim.x + threadIdx.x) >> 5;
    int lane = threadIdx.x & 31;
    if (gw >= NS) return;
    int is64 = s_s64;
    int half = lane >> 4, hl = lane & 15;

    float a[8];
#pragma unroll
    for (int i = 0; i < 8; i++) a[i] = 0.f;
    int cnt = 0;
    for (int l = half; l < NL; l += 2) {
        int idx = load_idx(sg, gw * NL + l, is64);
        if (idx >= 0) {
            cnt++;
            uint4 u = *(const uint4*)&g_h2h[idx * CF + hl * 8];
            float2 f0 = __half22float2(*reinterpret_cast<__half2*>(&u.x));
            float2 f1 = __half22float2(*reinterpret_cast<__half2*>(&u.y));
            float2 f2 = __half22float2(*reinterpret_cast<__half2*>(&u.z));
            float2 f3 = __half22float2(*reinterpret_cast<__half2*>(&u.w));
            a[0] += f0.x; a[1] += f0.y; a[2] += f1.x; a[3] += f1.y;
            a[4] += f2.x; a[5] += f2.y; a[6] += f3.x; a[7] += f3.y;
        }
    }
#pragma unroll
    for (int i = 0; i < 8; i++)
        a[i] += __shfl_down_sync(0xffffffffu, a[i], 16);
    cnt += __shfl_down_sync(0xffffffffu, cnt, 16);

    float inv = 1.0f / (float)(cnt > 0 ? cnt : 1);
#pragma unroll
    for (int i = 0; i < 8; i++) a[i] *= inv;

    float res[NCLS];
#pragma unroll
    for (int c = 0; c < NCLS; c++) {
        float v = 0.f;
#pragma unroll
        for (int i = 0; i < 8; i++) v += a[i] * Wc[(hl * 8 + i) * NCLS + c];
        res[c] = v;
    }
#pragma unroll
    for (int c = 0; c < NCLS; c++) {
        float v = res[c];
#pragma unroll
        for (int o = 8; o > 0; o >>= 1) v += __shfl_xor_sync(0xffffffffu, v, o);
        if (lane == 0) out[gw * NCLS + c] = v + bc[c];
    }
}

// ---------------- launch ----------------------------------------------------
extern "C" void kernel_launch(void* const* d_in, const int* in_sizes, int n_in,
                              void* d_out, int out_size) {
    const float* x  = (const float*)d_in[0];   // (N,1,128) contiguous
    const void*  ei = d_in[1];                 // (2,E) int64 or int32
    const void*  sg = d_in[2];                 // (S,64) int64 or int32
    const float* W1 = (const float*)d_in[3];
    const float* b1 = (const float*)d_in[4];
    const float* W2 = (const float*)d_in[5];
    const float* b2 = (const float*)d_in[6];
    const float* Wc = (const float*)d_in[7];
    const float* bc = (const float*)d_in[8];
    float* out = (float*)d_out;

    const int TB = 256;
    const int nbE = (NE + TB - 1) / TB;
    const int nbG = (NN + 127) / 128;
    const int nbA = (NN * 32 + TB - 1) / TB;   // warp per node
    const int nbP = (NS * 32 + TB - 1) / TB;   // warp per subgraph
    const int GEMM_SMEM = SM_TOTAL_HALVES * 2; // 55296 bytes

    cudaFuncSetAttribute(k_gemm_tc, cudaFuncAttributeMaxDynamicSharedMemorySize,
                         GEMM_SMEM);           // host-side, idempotent, capture-safe

    // Fork: GEMM1 depends only on inputs (x, W1) -> side stream, overlapping
    // the CSR-build chain; join before agg1.
    cudaStream_t s2;
    cudaEvent_t evF, evJ;
    cudaStreamCreateWithFlags(&s2, cudaStreamNonBlocking);
    cudaEventCreateWithFlags(&evF, cudaEventDisableTiming);
    cudaEventCreateWithFlags(&evJ, cudaEventDisableTiming);

    cudaEventRecord(evF, 0);
    cudaStreamWaitEvent(s2, evF, 0);

    // main-stream prep chain
    k_count<<<nbE, TB>>>(ei);                  // g_cnt pre-zeroed (init / k_scan3)
    k_scan1<<<SCAN_NB, SCAN_BS>>>();
    k_scan3<<<SCAN_NB, SCAN_BS>>>();
    k_fill<<<nbE, TB>>>(ei);

    // side-stream GEMM1 (overlaps the prep chain)
    k_gemm_tc<<<nbG, TB, GEMM_SMEM, s2>>>(x, W1, 0);   // hw = x @ W1 (fp16 out)
    cudaEventRecord(evJ, s2);
    cudaStreamWaitEvent(0, evJ, 0);            // join: agg1 needs hw + CSR

    k_agg<<<nbA, TB>>>(b1, 1, 1);              // h1 = relu(agg(hw) + b1)  (f32)
    k_gemm_tc<<<nbG, TB, GEMM_SMEM>>>(x, W2, 1);   // hw = h1 @ W2 (fp16 out)
    k_agg<<<nbA, TB>>>(b2, 2, 0);              // h2 = agg(hw) + b2        (f16)
    k_pool<<<nbP, TB>>>(sg, Wc, bc, out);
}